// round 10
// baseline (speedup 1.0000x reference)
#include <cuda_runtime.h>
#include <cuda_fp16.h>
#include <cstdint>

// Problem constants
#define BATCH 4
#define SEQ   8192
#define DIM   4096
#define NEXP  64
#define CAP   256
#define ROWS  (BATCH * SEQ)      // 32768

// GEMM tiling: 128 rows/CTA, 256 threads, KT=64, grid 256, 2 CTAs/SM
#define TILE_R 128
#define NTHR   256
#define KT     64
#define NCHUNK (DIM / KT)        // 64

// W pre-scaled by 2^10 in the pre-convert kernel; logits unscaled by 2^-10.
#define WSCALE   1024.0f
#define WUNSCALE 0.0009765625f

// smem: fp16 tiles, row stride 144 B (64 halves data + 8 pad) -> conflict-free
#define AS_BYTE 144
#define AHI_OFF 0
#define ALO_OFF 18432
#define BHI_OFF 36864
#define BLO_OFF 46080
#define BUF_STRIDE 55296
#define SMEM_BYTES (2 * BUF_STRIDE)   // 110592

// epilogue smem reuse
#define PS_STRIDE 130
#define RED_OFF   33280           // Ps = 64*130*4 bytes

// scratch
__device__ __half g_Whi[NEXP * DIM];                     // W hi (scaled)
__device__ __half g_Wlo[NEXP * DIM];                     // W lo (scaled)
__device__ float  g_probsT[(size_t)BATCH * NEXP * SEQ];  // [B][E][S]
__device__ float  g_thr[BATCH * NEXP];                   // per-(b,e) threshold

// ---------------------------------------------------------------------------
__device__ __forceinline__ uint32_t smem_u32(const void* p) {
    uint32_t a;
    asm("{ .reg .u64 t; cvta.to.shared.u64 t, %1; cvt.u32.u64 %0, t; }" : "=r"(a) : "l"(p));
    return a;
}
__device__ __forceinline__ void cp_async16(void* smem_dst, const void* gmem_src) {
    unsigned s = (unsigned)__cvta_generic_to_shared(smem_dst);
    asm volatile("cp.async.cg.shared.global [%0], [%1], 16;\n" :: "r"(s), "l"(gmem_src) : "memory");
}
__device__ __forceinline__ void cp_commit() {
    asm volatile("cp.async.commit_group;\n" ::: "memory");
}
__device__ __forceinline__ void cp_wait0() {
    asm volatile("cp.async.wait_group 0;\n" ::: "memory");
}

__device__ __forceinline__ void ldsm_x4(uint32_t& r0, uint32_t& r1, uint32_t& r2,
                                        uint32_t& r3, uint32_t addr) {
    asm volatile("ldmatrix.sync.aligned.m8n8.x4.shared.b16 {%0,%1,%2,%3}, [%4];"
                 : "=r"(r0), "=r"(r1), "=r"(r2), "=r"(r3) : "r"(addr));
}

__device__ __forceinline__ void mma_fp16(float* d, const uint32_t* a,
                                         uint32_t b0, uint32_t b1) {
    asm volatile("mma.sync.aligned.m16n8k16.row.col.f32.f16.f16.f32 "
                 "{%0,%1,%2,%3}, {%4,%5,%6,%7}, {%8,%9}, {%0,%1,%2,%3};"
                 : "+f"(d[0]), "+f"(d[1]), "+f"(d[2]), "+f"(d[3])
                 : "r"(a[0]), "r"(a[1]), "r"(a[2]), "r"(a[3]), "r"(b0), "r"(b1));
}

// ---------------------------------------------------------------------------
// Kernel 0: W fp32 -> scaled fp16 Dekker split (hi/lo), once.
// ---------------------------------------------------------------------------
__global__ void __launch_bounds__(256)
wconv_kernel(const float* __restrict__ W)
{
    int i = blockIdx.x * 256 + threadIdx.x;     // one float2 per thread
    float2 w = *(const float2*)(W + 2 * i);
    w.x *= WSCALE; w.y *= WSCALE;
    __half2 h = __floats2half2_rn(w.x, w.y);
    float rx = w.x - __half2float(__low2half(h));
    float ry = w.y - __half2float(__high2half(h));
    __half2 l = __floats2half2_rn(rx, ry);
    *(__half2*)(g_Whi + 2 * i) = h;
    *(__half2*)(g_Wlo + 2 * i) = l;
}

// ---------------------------------------------------------------------------
// Kernel 1: HMMA fp16-split router GEMM + fused softmax.
// 4x2 warp grid (warp 32 rows x 32 experts). X: LDG f32 -> reg -> split -> STS.
// B: cp.async fp16 directly from pre-converted g_Whi/g_Wlo (L2-resident).
// Grid 256 x 256 threads, 2 CTAs/SM.
// ---------------------------------------------------------------------------
__global__ void __launch_bounds__(NTHR, 2)
router_gemm_kernel(const float* __restrict__ X,
                   float* __restrict__ probs_out, float* __restrict__ logits_out)
{
    extern __shared__ char smem[];
    const uint32_t sbase = smem_u32(smem);
    const int tid  = threadIdx.x;
    const int wid  = tid >> 5;
    const int lane = tid & 31;
    const int wr   = wid & 3;     // row group (32 rows)
    const int wc   = wid >> 2;    // expert group (32 experts)
    const int row0 = blockIdx.x * TILE_R;

    float d[2][4][4];
#pragma unroll
    for (int mf = 0; mf < 2; mf++)
#pragma unroll
        for (int g = 0; g < 4; g++)
#pragma unroll
            for (int j = 0; j < 4; j++) d[mf][g][j] = 0.f;

    uint32_t a_off[2], b_off[2];
#pragma unroll
    for (int mf = 0; mf < 2; mf++)
        a_off[mf] = (uint32_t)((wr * 32 + mf * 16 + ((lane >> 3) & 1) * 8 + (lane & 7)) * AS_BYTE
                               + ((lane >> 4) & 1) * 16);
#pragma unroll
    for (int bg = 0; bg < 2; bg++)
        b_off[bg] = (uint32_t)((wc * 32 + bg * 16 + ((lane >> 4) & 1) * 8 + (lane & 7)) * AS_BYTE
                               + ((lane >> 3) & 1) * 16);

    // X staging: slot f = tid + m*256 -> row f>>4, float4-col f&15 (16 f4/row)
    const int sr = tid >> 4, sc4 = tid & 15;
    const float* Xg = X + (size_t)(row0 + sr) * DIM + sc4 * 4;   // +16 rows per m
    float4 xr[8];   // 128x64 f32 / 256 thr = 8 float4

    auto load_chunk = [&](int t) {
        const int k0 = t * KT;
#pragma unroll
        for (int m = 0; m < 8; m++)
            xr[m] = *(const float4*)(Xg + (size_t)(m * 16) * DIM + k0);
    };

    // B fill: 1024 x 16B copies (hi 512 + lo 512); 4 per thread.
    auto fill_B = [&](int t, int buf) {
        char* bp = smem + buf * BUF_STRIDE;
        const int k0 = t * KT;
#pragma unroll
        for (int m = 0; m < 4; m++) {
            int i = tid + m * 256;          // 0..1023
            int term = i >> 9;              // 0 = hi, 1 = lo
            int r    = (i & 511) >> 3;      // expert row 0..63
            int c16  = i & 7;               // 16B chunk within 128B data
            char* dst = bp + (term ? BLO_OFF : BHI_OFF) + r * AS_BYTE + c16 * 16;
            const __half* src = (term ? g_Wlo : g_Whi) + (size_t)r * DIM + k0 + c16 * 8;
            cp_async16(dst, src);
        }
    };

    auto split_store = [&](float4 v, char* hi_b, char* lo_b, uint32_t byte_off) {
        __half2 h0 = __floats2half2_rn(v.x, v.y);
        __half2 h1 = __floats2half2_rn(v.z, v.w);
        float rx = v.x - __half2float(__low2half(h0));
        float ry = v.y - __half2float(__high2half(h0));
        float rz = v.z - __half2float(__low2half(h1));
        float rw = v.w - __half2float(__high2half(h1));
        __half2 l0 = __floats2half2_rn(rx, ry);
        __half2 l1 = __floats2half2_rn(rz, rw);
        *(uint2*)(hi_b + byte_off) = make_uint2(*(uint32_t*)&h0, *(uint32_t*)&h1);
        *(uint2*)(lo_b + byte_off) = make_uint2(*(uint32_t*)&l0, *(uint32_t*)&l1);
    };

    auto store_chunk = [&](int buf) {
        char* bp = smem + buf * BUF_STRIDE;
        const uint32_t off0 = (uint32_t)(sr * AS_BYTE + sc4 * 8);
#pragma unroll
        for (int m = 0; m < 8; m++)
            split_store(xr[m], bp + AHI_OFF, bp + ALO_OFF, off0 + m * 16 * AS_BYTE);
    };

    auto compute_chunk = [&](int buf) {
        const uint32_t bb = sbase + buf * BUF_STRIDE;
#pragma unroll
        for (int ks = 0; ks < 4; ks++) {
            const uint32_t kb = ks * 32;    // k16 = 32 bytes
            uint32_t ah[2][4], al[2][4];
#pragma unroll
            for (int mf = 0; mf < 2; mf++) {
                ldsm_x4(ah[mf][0], ah[mf][1], ah[mf][2], ah[mf][3], bb + AHI_OFF + a_off[mf] + kb);
                ldsm_x4(al[mf][0], al[mf][1], al[mf][2], al[mf][3], bb + ALO_OFF + a_off[mf] + kb);
            }
#pragma unroll
            for (int bg = 0; bg < 2; bg++) {
                uint32_t bh[4], bl[4];
                ldsm_x4(bh[0], bh[1], bh[2], bh[3], bb + BHI_OFF + b_off[bg] + kb);
                ldsm_x4(bl[0], bl[1], bl[2], bl[3], bb + BLO_OFF + b_off[bg] + kb);
#pragma unroll
                for (int mf = 0; mf < 2; mf++) {
                    mma_fp16(d[mf][2 * bg],     ah[mf], bh[0], bh[1]);
                    mma_fp16(d[mf][2 * bg],     ah[mf], bl[0], bl[1]);
                    mma_fp16(d[mf][2 * bg],     al[mf], bh[0], bh[1]);
                    mma_fp16(d[mf][2 * bg + 1], ah[mf], bh[2], bh[3]);
                    mma_fp16(d[mf][2 * bg + 1], ah[mf], bl[2], bl[3]);
                    mma_fp16(d[mf][2 * bg + 1], al[mf], bh[2], bh[3]);
                }
            }
        }
    };

    // prologue: B(0)+X(0) into buf0
    fill_B(0, 0); cp_commit();
    load_chunk(0);
    store_chunk(0);
    cp_wait0();
    __syncthreads();

    for (int t = 0; t < NCHUNK; t++) {
        // buf (t+1)&1 held chunk t-1 (done) -> safe to refill asynchronously
        if (t + 1 < NCHUNK) { fill_B(t + 1, (t + 1) & 1); cp_commit(); }
        if (t + 1 < NCHUNK) load_chunk(t + 1);       // LDG early
        compute_chunk(t & 1);
        if (t + 1 < NCHUNK) { store_chunk((t + 1) & 1); cp_wait0(); }
        __syncthreads();
    }

    // ------------------------------------------------------------------
    // Epilogue: softmax across the 2 expert-group warps via smem exchange.
    // ------------------------------------------------------------------
    float* Ps     = (float*)smem;                 // [64][130]
    float* sm_max = (float*)(smem + RED_OFF);     // [128][2]
    float* sm_sum = sm_max + 256;                 // [128][2]
    const int q  = lane >> 2;
    const int c2 = (lane & 3) * 2;
    float pmax[2][2];

#pragma unroll
    for (int mf = 0; mf < 2; mf++)
#pragma unroll
    for (int half = 0; half < 2; half++) {
        const int r = wr * 32 + mf * 16 + q + half * 8;
        float v[8];
#pragma unroll
        for (int g = 0; g < 4; g++) {
            v[2 * g]     = d[mf][g][2 * half]     * WUNSCALE;
            v[2 * g + 1] = d[mf][g][2 * half + 1] * WUNSCALE;
        }
        float mx = v[0];
#pragma unroll
        for (int c = 1; c < 8; c++) mx = fmaxf(mx, v[c]);
        mx = fmaxf(mx, __shfl_xor_sync(0xFFFFFFFFu, mx, 1));
        mx = fmaxf(mx, __shfl_xor_sync(0xFFFFFFFFu, mx, 2));
        float ssum = 0.f;
#pragma unroll
        for (int c = 0; c < 8; c++) {
            float e = expf(v[c] - mx);
            d[mf][c >> 1][2 * half + (c & 1)] = e;   // cache exp
            ssum += e;
        }
        ssum += __shfl_xor_sync(0xFFFFFFFFu, ssum, 1);
        ssum += __shfl_xor_sync(0xFFFFFFFFu, ssum, 2);
        pmax[mf][half] = mx;

        const size_t grow = (size_t)(row0 + r) * NEXP + wc * 32;
#pragma unroll
        for (int g = 0; g < 4; g++)
            *(float2*)(logits_out + grow + g * 8 + c2) = make_float2(v[2 * g], v[2 * g + 1]);

        if ((lane & 3) == 0) {
            sm_max[r * 2 + wc] = mx;
            sm_sum[r * 2 + wc] = ssum;
        }
    }
    __syncthreads();

#pragma unroll
    for (int mf = 0; mf < 2; mf++)
#pragma unroll
    for (int half = 0; half < 2; half++) {
        const int r = wr * 32 + mf * 16 + q + half * 8;
        float m0 = sm_max[r * 2], m1 = sm_max[r * 2 + 1];
        float s0 = sm_sum[r * 2], s1 = sm_sum[r * 2 + 1];
        float M = fmaxf(m0, m1);
        float S = s0 * expf(m0 - M) + s1 * expf(m1 - M);
        float scale = expf(pmax[mf][half] - M) / S;

        const size_t grow = (size_t)(row0 + r) * NEXP + wc * 32;
#pragma unroll
        for (int g = 0; g < 4; g++) {
            const int col = wc * 32 + g * 8 + c2;
            float p0 = d[mf][g][2 * half]     * scale;
            float p1 = d[mf][g][2 * half + 1] * scale;
            *(float2*)(probs_out + grow + g * 8 + c2) = make_float2(p0, p1);
            Ps[col * PS_STRIDE + r]       = p0;
            Ps[(col + 1) * PS_STRIDE + r] = p1;
        }
    }
    __syncthreads();

    // coalesced transpose write: g_probsT[b][e][s]
    const int bb2 = row0 >> 13;
    const int s0i = row0 & (SEQ - 1);
#pragma unroll
    for (int m = 0; m < 32; m++) {
        int idx = tid + m * NTHR;       // 0..8191
        int e = idx >> 7, r = idx & 127;
        g_probsT[((size_t)(bb2 * NEXP + e)) * SEQ + s0i + r] = Ps[e * PS_STRIDE + r];
    }
}

// ---------------------------------------------------------------------------
// Kernel 2: per-(b,e) exact top-CAP radix-select threshold -> g_thr.
// ---------------------------------------------------------------------------
__global__ void __launch_bounds__(512)
thr_kernel()
{
    __shared__ unsigned vals[SEQ];
    __shared__ unsigned hist[256];
    __shared__ unsigned suff[256];
    __shared__ unsigned sel_prefix, sel_remaining;

    const int be  = blockIdx.x;
    const int tid = threadIdx.x;
    const unsigned* col = (const unsigned*)(g_probsT + (size_t)be * SEQ);

    for (int i = tid; i < SEQ; i += 512) vals[i] = col[i];
    if (tid == 0) { sel_prefix = 0u; sel_remaining = CAP; }
    __syncthreads();

    for (int pass = 0; pass < 4; pass++) {
        const int shift = 24 - 8 * pass;
        const unsigned himask = pass ? (0xFFFFFFFFu << (shift + 8)) : 0u;
        if (tid < 256) hist[tid] = 0u;
        __syncthreads();
        const unsigned pfx = sel_prefix;
        const unsigned rem = sel_remaining;
        for (int i = tid; i < SEQ; i += 512) {
            unsigned u = vals[i];
            if ((u & himask) == pfx)
                atomicAdd(&hist[(u >> shift) & 255u], 1u);
        }
        __syncthreads();
        if (tid < 256) suff[tid] = hist[tid];
        __syncthreads();
#pragma unroll
        for (int off = 1; off < 256; off <<= 1) {
            unsigned u = 0;
            if (tid < 256) u = suff[tid] + ((tid + off < 256) ? suff[tid + off] : 0u);
            __syncthreads();
            if (tid < 256) suff[tid] = u;
            __syncthreads();
        }
        if (tid < 256) {
            unsigned below = (tid < 255) ? suff[tid + 1] : 0u;
            if (suff[tid] >= rem && below < rem) {
                sel_prefix = pfx | ((unsigned)tid << shift);
                sel_remaining = rem - below;
            }
        }
        __syncthreads();
    }

    if (tid == 0) g_thr[be] = __uint_as_float(sel_prefix);
}

// ---------------------------------------------------------------------------
// Kernel 3: dense mask fill. mask[b,s,0] = any_e(probs[b,s,e] >= thr[b,e]).
// ---------------------------------------------------------------------------
__global__ void __launch_bounds__(512)
maskfill_kernel(const float* __restrict__ probs, float* __restrict__ mask)
{
    __shared__ float thr[NEXP];
    const int tid  = threadIdx.x;
    const int lane = tid & 31;
    const int wid  = tid >> 5;
    const int tok0 = blockIdx.x * 512;          // 512 tokens per block, same batch
    const int b    = tok0 >> 13;

    if (tid < NEXP) thr[tid] = g_thr[b * NEXP + tid];
    __syncthreads();

    const float t0 = thr[2 * lane], t1 = thr[2 * lane + 1];
    for (int i = 0; i < 32; i++) {
        const int tok = tok0 + wid * 32 + i;
        float2 p = *(const float2*)(probs + (size_t)tok * NEXP + 2 * lane);
        bool sel = (p.x >= t0) || (p.y >= t1);
        unsigned any = __ballot_sync(0xFFFFFFFFu, sel);
        float2 o = make_float2(0.f, 0.f);
        if (lane == 0 && any) o.x = 1.0f;
        *(float2*)(mask + (size_t)tok * NEXP + 2 * lane) = o;
    }
}

// ---------------------------------------------------------------------------
extern "C" void kernel_launch(void* const* d_in, const int* in_sizes, int n_in,
                              void* d_out, int out_size)
{
    const float* X = (const float*)d_in[0];   // [4, 8192, 4096]
    const float* W = (const float*)d_in[1];   // [64, 4096]

    float* mask   = (float*)d_out;
    float* probs  = mask  + (size_t)BATCH * SEQ * NEXP;
    float* logits = probs + (size_t)BATCH * SEQ * NEXP;

    // W -> scaled fp16 hi/lo (131072 float2 elems / 256 = 512 blocks)
    wconv_kernel<<<(NEXP * DIM / 2) / 256, 256>>>(W);

    cudaFuncSetAttribute(router_gemm_kernel,
                         cudaFuncAttributeMaxDynamicSharedMemorySize, SMEM_BYTES);
    router_gemm_kernel<<<ROWS / TILE_R, NTHR, SMEM_BYTES>>>(X, probs, logits);

    thr_kernel<<<BATCH * NEXP, 512>>>();

    maskfill_kernel<<<ROWS / 512, 512>>>(probs, mask);
}

// round 11
// speedup vs baseline: 1.0156x; 1.0156x over previous
#include <cuda_runtime.h>
#include <cuda_fp16.h>
#include <cstdint>

// Problem constants
#define BATCH 4
#define SEQ   8192
#define DIM   4096
#define NEXP  64
#define CAP   256
#define ROWS  (BATCH * SEQ)      // 32768

// GEMM tiling: 128 rows/CTA, 256 threads, KT=64 (2 half-phases), 2 CTAs/SM
#define TILE_R 128
#define NTHR   256
#define KT     64
#define NCHUNK (DIM / KT)        // 64

// W pre-scaled by 2^10 before fp16 split; logits unscaled by 2^-10 (exact).
#define WSCALE   1024.0f
#define WUNSCALE 0.0009765625f

// smem: fp16 tiles, row stride 144 B (64 halves data + 8 pad) -> ldmatrix
// conflict-free (row phase r*9 mod 8 = r mod 8: all 8 rows distinct 16B banks)
#define AS_BYTE 144
#define AHI_OFF 0
#define ALO_OFF 18432
#define BHI_OFF 36864
#define BLO_OFF 46080
#define BUF_STRIDE 55296
#define SMEM_BYTES (2 * BUF_STRIDE)   // 110592 -> 2 CTAs/SM (221KB <= 228KB)

// epilogue smem reuse
#define PS_STRIDE 130
#define RED_OFF   33280           // Ps = 64*130*4 bytes

// scratch
__device__ float g_probsT[(size_t)BATCH * NEXP * SEQ];   // [B][E][S]
__device__ float g_thr[BATCH * NEXP];                    // per-(b,e) threshold

// ---------------------------------------------------------------------------
__device__ __forceinline__ uint32_t smem_u32(const void* p) {
    uint32_t a;
    asm("{ .reg .u64 t; cvta.to.shared.u64 t, %1; cvt.u32.u64 %0, t; }" : "=r"(a) : "l"(p));
    return a;
}

__device__ __forceinline__ void ldsm_x4(uint32_t& r0, uint32_t& r1, uint32_t& r2,
                                        uint32_t& r3, uint32_t addr) {
    asm volatile("ldmatrix.sync.aligned.m8n8.x4.shared.b16 {%0,%1,%2,%3}, [%4];"
                 : "=r"(r0), "=r"(r1), "=r"(r2), "=r"(r3) : "r"(addr));
}

__device__ __forceinline__ void mma_fp16(float* d, const uint32_t* a,
                                         uint32_t b0, uint32_t b1) {
    asm volatile("mma.sync.aligned.m16n8k16.row.col.f32.f16.f16.f32 "
                 "{%0,%1,%2,%3}, {%4,%5,%6,%7}, {%8,%9}, {%0,%1,%2,%3};"
                 : "+f"(d[0]), "+f"(d[1]), "+f"(d[2]), "+f"(d[3])
                 : "r"(a[0]), "r"(a[1]), "r"(a[2]), "r"(a[3]), "r"(b0), "r"(b1));
}

// ---------------------------------------------------------------------------
// Kernel 1: HMMA fp16-split router GEMM + fused softmax.
// R6 structure, KT=64: per iteration, two (load-half / compute-2ks / store-half)
// phases -> 64 barriers instead of 128, LDG covered by interleaved compute,
// staging register footprint identical to R6 (6 float4 live).
// 4x2 warp grid (warp 32 rows x 32 experts). Grid 256 x 256 thr, 2 CTAs/SM.
// ---------------------------------------------------------------------------
__global__ void __launch_bounds__(NTHR, 2)
router_gemm_kernel(const float* __restrict__ X, const float* __restrict__ W,
                   float* __restrict__ probs_out, float* __restrict__ logits_out)
{
    extern __shared__ char smem[];
    const uint32_t sbase = smem_u32(smem);
    const int tid  = threadIdx.x;
    const int wid  = tid >> 5;
    const int lane = tid & 31;
    const int wr   = wid & 3;     // row group (32 rows)
    const int wc   = wid >> 2;    // expert group (32 experts)
    const int row0 = blockIdx.x * TILE_R;

    float d[2][4][4];
#pragma unroll
    for (int mf = 0; mf < 2; mf++)
#pragma unroll
        for (int g = 0; g < 4; g++)
#pragma unroll
            for (int j = 0; j < 4; j++) d[mf][g][j] = 0.f;

    uint32_t a_off[2], b_off[2];
#pragma unroll
    for (int mf = 0; mf < 2; mf++)
        a_off[mf] = (uint32_t)((wr * 32 + mf * 16 + ((lane >> 3) & 1) * 8 + (lane & 7)) * AS_BYTE
                               + ((lane >> 4) & 1) * 16);
#pragma unroll
    for (int bg = 0; bg < 2; bg++)
        b_off[bg] = (uint32_t)((wc * 32 + bg * 16 + ((lane >> 4) & 1) * 8 + (lane & 7)) * AS_BYTE
                               + ((lane >> 3) & 1) * 16);

    // staging addressing: slot f = tid + m*256 -> row f>>4 (16 float4 per row)
    const int sr = tid >> 4, sc4 = tid & 15;
    const float* Xg = X + (size_t)(row0 + sr) * DIM + sc4 * 4;
    const float* Wg = W + (size_t)sr * DIM + sc4 * 4;

    // half staging: X 4 float4 (64 rows), W 2 float4 (32 experts) = 24 regs
    float4 xr[4];
    float4 wr4[2];

    // rhalf: 0 -> X rows 0..63 / W rows 0..31 ; 1 -> X rows 64..127 / W 32..63
    auto load_half = [&](int t, int rhalf) {
        const int k0 = t * KT;
        const int xrow = rhalf * 64, wrow = rhalf * 32;
#pragma unroll
        for (int m = 0; m < 4; m++)
            xr[m] = *(const float4*)(Xg + (size_t)(xrow + m * 16) * DIM + k0);
#pragma unroll
        for (int m = 0; m < 2; m++)
            wr4[m] = *(const float4*)(Wg + (size_t)(wrow + m * 16) * DIM + k0);
    };

    auto split_store = [&](float4 v, char* hi_b, char* lo_b, uint32_t byte_off) {
        __half2 h0 = __floats2half2_rn(v.x, v.y);
        __half2 h1 = __floats2half2_rn(v.z, v.w);
        float rx = v.x - __half2float(__low2half(h0));
        float ry = v.y - __half2float(__high2half(h0));
        float rz = v.z - __half2float(__low2half(h1));
        float rw = v.w - __half2float(__high2half(h1));
        __half2 l0 = __floats2half2_rn(rx, ry);
        __half2 l1 = __floats2half2_rn(rz, rw);
        *(uint2*)(hi_b + byte_off) = make_uint2(*(uint32_t*)&h0, *(uint32_t*)&h1);
        *(uint2*)(lo_b + byte_off) = make_uint2(*(uint32_t*)&l0, *(uint32_t*)&l1);
    };

    auto store_half = [&](int buf, int rhalf) {
        char* bp = smem + buf * BUF_STRIDE;
        const uint32_t xoff = (uint32_t)((rhalf * 64 + sr) * AS_BYTE + sc4 * 8);
        const uint32_t woff = (uint32_t)((rhalf * 32 + sr) * AS_BYTE + sc4 * 8);
#pragma unroll
        for (int m = 0; m < 4; m++)
            split_store(xr[m], bp + AHI_OFF, bp + ALO_OFF, xoff + m * 16 * AS_BYTE);
#pragma unroll
        for (int m = 0; m < 2; m++) {
            float4 v = wr4[m];
            v.x *= WSCALE; v.y *= WSCALE; v.z *= WSCALE; v.w *= WSCALE;
            split_store(v, bp + BHI_OFF, bp + BLO_OFF, woff + m * 16 * AS_BYTE);
        }
    };

    // two k16 steps (half the chunk)
    auto compute_half = [&](int buf, int ks_base) {
        const uint32_t bb = sbase + buf * BUF_STRIDE;
#pragma unroll
        for (int ks = ks_base; ks < ks_base + 2; ks++) {
            const uint32_t kb = ks * 32;    // k16 = 32 bytes
            uint32_t ah[2][4], al[2][4];
#pragma unroll
            for (int mf = 0; mf < 2; mf++) {
                ldsm_x4(ah[mf][0], ah[mf][1], ah[mf][2], ah[mf][3], bb + AHI_OFF + a_off[mf] + kb);
                ldsm_x4(al[mf][0], al[mf][1], al[mf][2], al[mf][3], bb + ALO_OFF + a_off[mf] + kb);
            }
#pragma unroll
            for (int bg = 0; bg < 2; bg++) {
                uint32_t bh[4], bl[4];
                ldsm_x4(bh[0], bh[1], bh[2], bh[3], bb + BHI_OFF + b_off[bg] + kb);
                ldsm_x4(bl[0], bl[1], bl[2], bl[3], bb + BLO_OFF + b_off[bg] + kb);
#pragma unroll
                for (int mf = 0; mf < 2; mf++) {
                    mma_fp16(d[mf][2 * bg],     ah[mf], bh[0], bh[1]);
                    mma_fp16(d[mf][2 * bg],     ah[mf], bl[0], bl[1]);
                    mma_fp16(d[mf][2 * bg],     al[mf], bh[0], bh[1]);
                    mma_fp16(d[mf][2 * bg + 1], ah[mf], bh[2], bh[3]);
                    mma_fp16(d[mf][2 * bg + 1], ah[mf], bl[2], bl[3]);
                    mma_fp16(d[mf][2 * bg + 1], al[mf], bh[2], bh[3]);
                }
            }
        }
    };

    // prologue: chunk 0 -> buf 0
    load_half(0, 0); store_half(0, 0);
    load_half(0, 1); store_half(0, 1);
    __syncthreads();

    for (int t = 0; t < NCHUNK; t++) {
        const int buf = t & 1, nbuf = (t + 1) & 1;
        const bool more = (t + 1 < NCHUNK);
        if (more) load_half(t + 1, 0);      // LDG issues, covered by compute
        compute_half(buf, 0);               // ks 0,1
        if (more) { store_half(nbuf, 0); load_half(t + 1, 1); }
        compute_half(buf, 2);               // ks 2,3
        if (more) store_half(nbuf, 1);
        __syncthreads();
    }

    // ------------------------------------------------------------------
    // Epilogue: softmax across the 2 expert-group warps via smem exchange.
    // ------------------------------------------------------------------
    float* Ps     = (float*)smem;                 // [64][130]
    float* sm_max = (float*)(smem + RED_OFF);     // [128][2]
    float* sm_sum = sm_max + 256;                 // [128][2]
    const int q  = lane >> 2;
    const int c2 = (lane & 3) * 2;
    float pmax[2][2];

#pragma unroll
    for (int mf = 0; mf < 2; mf++)
#pragma unroll
    for (int half = 0; half < 2; half++) {
        const int r = wr * 32 + mf * 16 + q + half * 8;
        float v[8];
#pragma unroll
        for (int g = 0; g < 4; g++) {
            v[2 * g]     = d[mf][g][2 * half]     * WUNSCALE;
            v[2 * g + 1] = d[mf][g][2 * half + 1] * WUNSCALE;
        }
        float mx = v[0];
#pragma unroll
        for (int c = 1; c < 8; c++) mx = fmaxf(mx, v[c]);
        mx = fmaxf(mx, __shfl_xor_sync(0xFFFFFFFFu, mx, 1));
        mx = fmaxf(mx, __shfl_xor_sync(0xFFFFFFFFu, mx, 2));
        float ssum = 0.f;
#pragma unroll
        for (int c = 0; c < 8; c++) {
            float e = expf(v[c] - mx);
            d[mf][c >> 1][2 * half + (c & 1)] = e;   // cache exp
            ssum += e;
        }
        ssum += __shfl_xor_sync(0xFFFFFFFFu, ssum, 1);
        ssum += __shfl_xor_sync(0xFFFFFFFFu, ssum, 2);
        pmax[mf][half] = mx;

        const size_t grow = (size_t)(row0 + r) * NEXP + wc * 32;
#pragma unroll
        for (int g = 0; g < 4; g++)
            *(float2*)(logits_out + grow + g * 8 + c2) = make_float2(v[2 * g], v[2 * g + 1]);

        if ((lane & 3) == 0) {
            sm_max[r * 2 + wc] = mx;
            sm_sum[r * 2 + wc] = ssum;
        }
    }
    __syncthreads();

#pragma unroll
    for (int mf = 0; mf < 2; mf++)
#pragma unroll
    for (int half = 0; half < 2; half++) {
        const int r = wr * 32 + mf * 16 + q + half * 8;
        float m0 = sm_max[r * 2], m1 = sm_max[r * 2 + 1];
        float s0 = sm_sum[r * 2], s1 = sm_sum[r * 2 + 1];
        float M = fmaxf(m0, m1);
        float S = s0 * expf(m0 - M) + s1 * expf(m1 - M);
        float scale = expf(pmax[mf][half] - M) / S;

        const size_t grow = (size_t)(row0 + r) * NEXP + wc * 32;
#pragma unroll
        for (int g = 0; g < 4; g++) {
            const int col = wc * 32 + g * 8 + c2;
            float p0 = d[mf][g][2 * half]     * scale;
            float p1 = d[mf][g][2 * half + 1] * scale;
            *(float2*)(probs_out + grow + g * 8 + c2) = make_float2(p0, p1);
            Ps[col * PS_STRIDE + r]       = p0;
            Ps[(col + 1) * PS_STRIDE + r] = p1;
        }
    }
    __syncthreads();

    // coalesced transpose write: g_probsT[b][e][s]
    const int bb2 = row0 >> 13;
    const int s0i = row0 & (SEQ - 1);
#pragma unroll
    for (int m = 0; m < 32; m++) {
        int idx = tid + m * NTHR;       // 0..8191
        int e = idx >> 7, r = idx & 127;
        g_probsT[((size_t)(bb2 * NEXP + e)) * SEQ + s0i + r] = Ps[e * PS_STRIDE + r];
    }
}

// ---------------------------------------------------------------------------
// Kernel 2: per-(b,e) exact top-CAP radix-select threshold -> g_thr.
// Bin search now a single-warp suffix scan (no block-wide scan syncs).
// ---------------------------------------------------------------------------
__global__ void __launch_bounds__(512)
thr_kernel()
{
    __shared__ unsigned vals[SEQ];
    __shared__ unsigned hist[256];
    __shared__ unsigned sel_prefix, sel_remaining;

    const int be  = blockIdx.x;
    const int tid = threadIdx.x;
    const int lane = tid & 31;
    const unsigned* col = (const unsigned*)(g_probsT + (size_t)be * SEQ);

    for (int i = tid; i < SEQ; i += 512) vals[i] = col[i];
    if (tid == 0) { sel_prefix = 0u; sel_remaining = CAP; }
    __syncthreads();

    for (int pass = 0; pass < 4; pass++) {
        const int shift = 24 - 8 * pass;
        const unsigned himask = pass ? (0xFFFFFFFFu << (shift + 8)) : 0u;
        if (tid < 256) hist[tid] = 0u;
        __syncthreads();
        const unsigned pfx = sel_prefix;
        for (int i = tid; i < SEQ; i += 512) {
            unsigned u = vals[i];
            if ((u & himask) == pfx)
                atomicAdd(&hist[(u >> shift) & 255u], 1u);
        }
        __syncthreads();

        if (tid < 32) {
            // lane owns bins [lane*8, lane*8+8)
            unsigned b[8], s[8];
#pragma unroll
            for (int k = 0; k < 8; k++) b[k] = hist[lane * 8 + k];
            s[7] = b[7];
#pragma unroll
            for (int k = 6; k >= 0; k--) s[k] = b[k] + s[k + 1];
            unsigned T = s[0];
            unsigned incl = T;              // sum over lanes >= lane
#pragma unroll
            for (int off = 1; off < 32; off <<= 1) {
                unsigned v = __shfl_down_sync(0xFFFFFFFFu, incl, off);
                if (lane + off < 32) incl += v;
            }
            const unsigned excl = incl - T; // sum over lanes > lane
            const unsigned rem = sel_remaining;
#pragma unroll
            for (int k = 0; k < 8; k++) {
                unsigned suf = excl + s[k];     // suffix incl bin (lane*8+k)
                unsigned nxt = suf - b[k];
                if (suf >= rem && nxt < rem) {  // exactly one (lane,k) matches
                    sel_prefix = pfx | ((unsigned)(lane * 8 + k) << shift);
                    sel_remaining = rem - nxt;
                }
            }
        }
        __syncthreads();
    }

    if (tid == 0) g_thr[be] = __uint_as_float(sel_prefix);
}

// ---------------------------------------------------------------------------
// Kernel 3: dense mask fill, loop-free: one warp per token.
// mask[b,s,0] = any_e(probs[b,s,e] >= thr[b,e]); other channels 0.
// ---------------------------------------------------------------------------
__global__ void __launch_bounds__(256)
maskfill_kernel(const float* __restrict__ probs, float* __restrict__ mask)
{
    __shared__ float thr[NEXP];
    const int tid  = threadIdx.x;
    const int lane = tid & 31;
    const int wid  = tid >> 5;
    const int tok  = blockIdx.x * 8 + wid;      // 8 tokens per block
    const int b    = (blockIdx.x * 8) >> 13;    // same batch across block

    if (tid < NEXP) thr[tid] = g_thr[b * NEXP + tid];
    __syncthreads();

    float2 p = *(const float2*)(probs + (size_t)tok * NEXP + 2 * lane);
    bool sel = (p.x >= thr[2 * lane]) || (p.y >= thr[2 * lane + 1]);
    unsigned any = __ballot_sync(0xFFFFFFFFu, sel);
    float2 o = make_float2(0.f, 0.f);
    if (lane == 0 && any) o.x = 1.0f;
    *(float2*)(mask + (size_t)tok * NEXP + 2 * lane) = o;
}

// ---------------------------------------------------------------------------
extern "C" void kernel_launch(void* const* d_in, const int* in_sizes, int n_in,
                              void* d_out, int out_size)
{
    const float* X = (const float*)d_in[0];   // [4, 8192, 4096]
    const float* W = (const float*)d_in[1];   // [64, 4096]

    float* mask   = (float*)d_out;
    float* probs  = mask  + (size_t)BATCH * SEQ * NEXP;
    float* logits = probs + (size_t)BATCH * SEQ * NEXP;

    cudaFuncSetAttribute(router_gemm_kernel,
                         cudaFuncAttributeMaxDynamicSharedMemorySize, SMEM_BYTES);
    router_gemm_kernel<<<ROWS / TILE_R, NTHR, SMEM_BYTES>>>(X, W, probs, logits);

    thr_kernel<<<BATCH * NEXP, 512>>>();

    maskfill_kernel<<<ROWS / 8, 256>>>(probs, mask);
}

// round 12
// speedup vs baseline: 1.1582x; 1.1404x over previous
#include <cuda_runtime.h>
#include <cuda_fp16.h>
#include <cstdint>

// Problem constants
#define BATCH 4
#define SEQ   8192
#define DIM   4096
#define NEXP  64
#define CAP   256
#define ROWS  (BATCH * SEQ)      // 32768

// GEMM tiling (R6 config — best measured): 128 rows/CTA, 256 thr, KT=32, 2 CTA/SM
#define TILE_R 128
#define NTHR   256
#define KT     32
#define NCHUNK (DIM / KT)        // 128

// W pre-scaled by 2^10 before fp16 split; logits unscaled by 2^-10 (exact).
#define WSCALE   1024.0f
#define WUNSCALE 0.0009765625f

// smem: fp16 tiles, row stride 40 halves (80 bytes) -> conflict-free ldmatrix
#define AS_BYTE 80
#define AHI_OFF 0
#define ALO_OFF 10240
#define BHI_OFF 20480
#define BLO_OFF 25600
#define BUF_STRIDE 30720
#define SMEM_BYTES (2 * BUF_STRIDE)   // 61440

// epilogue smem reuse
#define PS_STRIDE 130
#define RED_OFF   34048           // Ps = 64*130*4 = 33280

// scratch
__device__ float g_probsT[(size_t)BATCH * NEXP * SEQ];   // [B][E][S]
__device__ float g_thr[BATCH * NEXP];                    // per-(b,e) threshold

// ---------------------------------------------------------------------------
__device__ __forceinline__ uint32_t smem_u32(const void* p) {
    uint32_t a;
    asm("{ .reg .u64 t; cvta.to.shared.u64 t, %1; cvt.u32.u64 %0, t; }" : "=r"(a) : "l"(p));
    return a;
}

__device__ __forceinline__ void ldsm_x4(uint32_t& r0, uint32_t& r1, uint32_t& r2,
                                        uint32_t& r3, uint32_t addr) {
    asm volatile("ldmatrix.sync.aligned.m8n8.x4.shared.b16 {%0,%1,%2,%3}, [%4];"
                 : "=r"(r0), "=r"(r1), "=r"(r2), "=r"(r3) : "r"(addr));
}

__device__ __forceinline__ void mma_fp16(float* d, const uint32_t* a,
                                         uint32_t b0, uint32_t b1) {
    asm volatile("mma.sync.aligned.m16n8k16.row.col.f32.f16.f16.f32 "
                 "{%0,%1,%2,%3}, {%4,%5,%6,%7}, {%8,%9}, {%0,%1,%2,%3};"
                 : "+f"(d[0]), "+f"(d[1]), "+f"(d[2]), "+f"(d[3])
                 : "r"(a[0]), "r"(a[1]), "r"(a[2]), "r"(a[3]), "r"(b0), "r"(b1));
}

// ---------------------------------------------------------------------------
// Kernel 1: HMMA fp16-split router GEMM + fused softmax (R6 config).
// 4x2 warp grid: warp (wr, wc) computes rows [wr*32,+32) x experts [wc*32,+32).
// Grid 256 x 256 threads, 2 CTAs/SM.
// ---------------------------------------------------------------------------
__global__ void __launch_bounds__(NTHR, 2)
router_gemm_kernel(const float* __restrict__ X, const float* __restrict__ W,
                   float* __restrict__ probs_out, float* __restrict__ logits_out)
{
    extern __shared__ char smem[];
    const uint32_t sbase = smem_u32(smem);
    const int tid  = threadIdx.x;
    const int wid  = tid >> 5;
    const int lane = tid & 31;
    const int wr   = wid & 3;     // row group (32 rows)
    const int wc   = wid >> 2;    // expert group (32 experts)
    const int row0 = blockIdx.x * TILE_R;

    float d[2][4][4];
#pragma unroll
    for (int mf = 0; mf < 2; mf++)
#pragma unroll
        for (int g = 0; g < 4; g++)
#pragma unroll
            for (int j = 0; j < 4; j++) d[mf][g][j] = 0.f;

    uint32_t a_off[2], b_off[2];
#pragma unroll
    for (int mf = 0; mf < 2; mf++)
        a_off[mf] = (uint32_t)((wr * 32 + mf * 16 + ((lane >> 3) & 1) * 8 + (lane & 7)) * AS_BYTE
                               + ((lane >> 4) & 1) * 16);
#pragma unroll
    for (int bg = 0; bg < 2; bg++)
        b_off[bg] = (uint32_t)((wc * 32 + bg * 16 + ((lane >> 4) & 1) * 8 + (lane & 7)) * AS_BYTE
                               + ((lane >> 3) & 1) * 16);

    // register staging for one K-chunk
    float4 xr[4];   // 128x32 fp32 / 256 thr = 4 float4
    float4 wr4[2];  //  64x32 fp32 / 256 thr = 2 float4

    auto load_chunk = [&](int t) {
        const int k0 = t * KT;
#pragma unroll
        for (int m = 0; m < 4; m++) {
            int f = tid + m * 256;           // float4 slot, 8 per row
            int r = f >> 3, c4 = f & 7;
            xr[m] = *(const float4*)(X + (size_t)(row0 + r) * DIM + k0 + c4 * 4);
        }
#pragma unroll
        for (int m = 0; m < 2; m++) {
            int f = tid + m * 256;
            int e = f >> 3, c4 = f & 7;
            wr4[m] = *(const float4*)(W + (size_t)e * DIM + k0 + c4 * 4);
        }
    };

    auto cvt_store = [&](float4 v, float scale, char* hi_b, char* lo_b, uint32_t byte_off) {
        v.x *= scale; v.y *= scale; v.z *= scale; v.w *= scale;
        __half2 h0 = __floats2half2_rn(v.x, v.y);
        __half2 h1 = __floats2half2_rn(v.z, v.w);
        float rx = v.x - __half2float(__low2half(h0));
        float ry = v.y - __half2float(__high2half(h0));
        float rz = v.z - __half2float(__low2half(h1));
        float rw = v.w - __half2float(__high2half(h1));
        __half2 l0 = __floats2half2_rn(rx, ry);
        __half2 l1 = __floats2half2_rn(rz, rw);
        *(uint2*)(hi_b + byte_off) = make_uint2(*(uint32_t*)&h0, *(uint32_t*)&h1);
        *(uint2*)(lo_b + byte_off) = make_uint2(*(uint32_t*)&l0, *(uint32_t*)&l1);
    };

    auto store_chunk = [&](int buf) {
        char* bp = smem + buf * BUF_STRIDE;
#pragma unroll
        for (int m = 0; m < 4; m++) {
            int f = tid + m * 256;
            int r = f >> 3, c4 = f & 7;
            cvt_store(xr[m], 1.0f, bp + AHI_OFF, bp + ALO_OFF, (uint32_t)(r * AS_BYTE + c4 * 8));
        }
#pragma unroll
        for (int m = 0; m < 2; m++) {
            int f = tid + m * 256;
            int e = f >> 3, c4 = f & 7;
            cvt_store(wr4[m], WSCALE, bp + BHI_OFF, bp + BLO_OFF, (uint32_t)(e * AS_BYTE + c4 * 8));
        }
    };

    auto compute_chunk = [&](int buf) {
        const uint32_t bb = sbase + buf * BUF_STRIDE;
#pragma unroll
        for (int ks = 0; ks < 2; ks++) {
            const uint32_t kb = ks * 32;
            uint32_t ah[2][4], al[2][4];
#pragma unroll
            for (int mf = 0; mf < 2; mf++) {
                ldsm_x4(ah[mf][0], ah[mf][1], ah[mf][2], ah[mf][3], bb + AHI_OFF + a_off[mf] + kb);
                ldsm_x4(al[mf][0], al[mf][1], al[mf][2], al[mf][3], bb + ALO_OFF + a_off[mf] + kb);
            }
#pragma unroll
            for (int bg = 0; bg < 2; bg++) {
                uint32_t bh[4], bl[4];
                ldsm_x4(bh[0], bh[1], bh[2], bh[3], bb + BHI_OFF + b_off[bg] + kb);
                ldsm_x4(bl[0], bl[1], bl[2], bl[3], bb + BLO_OFF + b_off[bg] + kb);
#pragma unroll
                for (int mf = 0; mf < 2; mf++) {
                    mma_fp16(d[mf][2 * bg],     ah[mf], bh[0], bh[1]);
                    mma_fp16(d[mf][2 * bg],     ah[mf], bl[0], bl[1]);
                    mma_fp16(d[mf][2 * bg],     al[mf], bh[0], bh[1]);
                    mma_fp16(d[mf][2 * bg + 1], ah[mf], bh[2], bh[3]);
                    mma_fp16(d[mf][2 * bg + 1], ah[mf], bl[2], bl[3]);
                    mma_fp16(d[mf][2 * bg + 1], al[mf], bh[2], bh[3]);
                }
            }
        }
    };

    load_chunk(0);
    store_chunk(0);
    __syncthreads();

    for (int t = 0; t < NCHUNK; t++) {
        if (t + 1 < NCHUNK) load_chunk(t + 1);       // LDG early
        compute_chunk(t & 1);                        // HMMA stretch hides LDG
        if (t + 1 < NCHUNK) store_chunk((t + 1) & 1);
        __syncthreads();
    }

    // ------------------------------------------------------------------
    // Epilogue: softmax across the 2 expert-group warps via smem exchange.
    // ------------------------------------------------------------------
    float* Ps     = (float*)smem;                 // [64][130]
    float* sm_max = (float*)(smem + RED_OFF);     // [128][2]
    float* sm_sum = sm_max + 256;                 // [128][2]
    const int q  = lane >> 2;
    const int c2 = (lane & 3) * 2;
    float pmax[2][2];

#pragma unroll
    for (int mf = 0; mf < 2; mf++)
#pragma unroll
    for (int half = 0; half < 2; half++) {
        const int r = wr * 32 + mf * 16 + q + half * 8;
        float v[8];
#pragma unroll
        for (int g = 0; g < 4; g++) {
            v[2 * g]     = d[mf][g][2 * half]     * WUNSCALE;
            v[2 * g + 1] = d[mf][g][2 * half + 1] * WUNSCALE;
        }
        float mx = v[0];
#pragma unroll
        for (int c = 1; c < 8; c++) mx = fmaxf(mx, v[c]);
        mx = fmaxf(mx, __shfl_xor_sync(0xFFFFFFFFu, mx, 1));
        mx = fmaxf(mx, __shfl_xor_sync(0xFFFFFFFFu, mx, 2));
        float ssum = 0.f;
#pragma unroll
        for (int c = 0; c < 8; c++) {
            float e = expf(v[c] - mx);
            d[mf][c >> 1][2 * half + (c & 1)] = e;   // cache exp
            ssum += e;
        }
        ssum += __shfl_xor_sync(0xFFFFFFFFu, ssum, 1);
        ssum += __shfl_xor_sync(0xFFFFFFFFu, ssum, 2);
        pmax[mf][half] = mx;

        const size_t grow = (size_t)(row0 + r) * NEXP + wc * 32;
#pragma unroll
        for (int g = 0; g < 4; g++)
            *(float2*)(logits_out + grow + g * 8 + c2) = make_float2(v[2 * g], v[2 * g + 1]);

        if ((lane & 3) == 0) {
            sm_max[r * 2 + wc] = mx;
            sm_sum[r * 2 + wc] = ssum;
        }
    }
    __syncthreads();

#pragma unroll
    for (int mf = 0; mf < 2; mf++)
#pragma unroll
    for (int half = 0; half < 2; half++) {
        const int r = wr * 32 + mf * 16 + q + half * 8;
        float m0 = sm_max[r * 2], m1 = sm_max[r * 2 + 1];
        float s0 = sm_sum[r * 2], s1 = sm_sum[r * 2 + 1];
        float M = fmaxf(m0, m1);
        float S = s0 * expf(m0 - M) + s1 * expf(m1 - M);
        float scale = expf(pmax[mf][half] - M) / S;

        const size_t grow = (size_t)(row0 + r) * NEXP + wc * 32;
#pragma unroll
        for (int g = 0; g < 4; g++) {
            const int col = wc * 32 + g * 8 + c2;
            float p0 = d[mf][g][2 * half]     * scale;
            float p1 = d[mf][g][2 * half + 1] * scale;
            *(float2*)(probs_out + grow + g * 8 + c2) = make_float2(p0, p1);
            Ps[col * PS_STRIDE + r]       = p0;
            Ps[(col + 1) * PS_STRIDE + r] = p1;
        }
    }
    __syncthreads();

    // coalesced transpose write: g_probsT[b][e][s]
    const int bb2 = row0 >> 13;
    const int s0i = row0 & (SEQ - 1);
#pragma unroll
    for (int m = 0; m < 32; m++) {
        int idx = tid + m * NTHR;       // 0..8191
        int e = idx >> 7, r = idx & 127;
        g_probsT[((size_t)(bb2 * NEXP + e)) * SEQ + s0i + r] = Ps[e * PS_STRIDE + r];
    }
}

// ---------------------------------------------------------------------------
// Kernel 2: per-(b,e) exact top-CAP radix-select threshold -> g_thr.
// Bin search: single-warp suffix scan (R11 version, measured fast).
// ---------------------------------------------------------------------------
__global__ void __launch_bounds__(512)
thr_kernel()
{
    __shared__ unsigned vals[SEQ];
    __shared__ unsigned hist[256];
    __shared__ unsigned sel_prefix, sel_remaining;

    const int be  = blockIdx.x;
    const int tid = threadIdx.x;
    const int lane = tid & 31;
    const unsigned* col = (const unsigned*)(g_probsT + (size_t)be * SEQ);

    for (int i = tid; i < SEQ; i += 512) vals[i] = col[i];
    if (tid == 0) { sel_prefix = 0u; sel_remaining = CAP; }
    __syncthreads();

    for (int pass = 0; pass < 4; pass++) {
        const int shift = 24 - 8 * pass;
        const unsigned himask = pass ? (0xFFFFFFFFu << (shift + 8)) : 0u;
        if (tid < 256) hist[tid] = 0u;
        __syncthreads();
        const unsigned pfx = sel_prefix;
        for (int i = tid; i < SEQ; i += 512) {
            unsigned u = vals[i];
            if ((u & himask) == pfx)
                atomicAdd(&hist[(u >> shift) & 255u], 1u);
        }
        __syncthreads();

        if (tid < 32) {
            unsigned b[8], s[8];
#pragma unroll
            for (int k = 0; k < 8; k++) b[k] = hist[lane * 8 + k];
            s[7] = b[7];
#pragma unroll
            for (int k = 6; k >= 0; k--) s[k] = b[k] + s[k + 1];
            unsigned T = s[0];
            unsigned incl = T;
#pragma unroll
            for (int off = 1; off < 32; off <<= 1) {
                unsigned v = __shfl_down_sync(0xFFFFFFFFu, incl, off);
                if (lane + off < 32) incl += v;
            }
            const unsigned excl = incl - T;
            const unsigned rem = sel_remaining;
#pragma unroll
            for (int k = 0; k < 8; k++) {
                unsigned suf = excl + s[k];
                unsigned nxt = suf - b[k];
                if (suf >= rem && nxt < rem) {
                    sel_prefix = pfx | ((unsigned)(lane * 8 + k) << shift);
                    sel_remaining = rem - nxt;
                }
            }
        }
        __syncthreads();
    }

    if (tid == 0) g_thr[be] = __uint_as_float(sel_prefix);
}

// ---------------------------------------------------------------------------
// Kernel 3: dense mask fill, loop-free: one warp per token (R11 version).
// mask[b,s,0] = any_e(probs[b,s,e] >= thr[b,e]); other channels 0.
// ---------------------------------------------------------------------------
__global__ void __launch_bounds__(256)
maskfill_kernel(const float* __restrict__ probs, float* __restrict__ mask)
{
    __shared__ float thr[NEXP];
    const int tid  = threadIdx.x;
    const int lane = tid & 31;
    const int wid  = tid >> 5;
    const int tok  = blockIdx.x * 8 + wid;      // 8 tokens per block
    const int b    = (blockIdx.x * 8) >> 13;    // same batch across block

    if (tid < NEXP) thr[tid] = g_thr[b * NEXP + tid];
    __syncthreads();

    float2 p = *(const float2*)(probs + (size_t)tok * NEXP + 2 * lane);
    bool sel = (p.x >= thr[2 * lane]) || (p.y >= thr[2 * lane + 1]);
    unsigned any = __ballot_sync(0xFFFFFFFFu, sel);
    float2 o = make_float2(0.f, 0.f);
    if (lane == 0 && any) o.x = 1.0f;
    *(float2*)(mask + (size_t)tok * NEXP + 2 * lane) = o;
}

// ---------------------------------------------------------------------------
extern "C" void kernel_launch(void* const* d_in, const int* in_sizes, int n_in,
                              void* d_out, int out_size)
{
    const float* X = (const float*)d_in[0];   // [4, 8192, 4096]
    const float* W = (const float*)d_in[1];   // [64, 4096]

    float* mask   = (float*)d_out;
    float* probs  = mask  + (size_t)BATCH * SEQ * NEXP;
    float* logits = probs + (size_t)BATCH * SEQ * NEXP;

    cudaFuncSetAttribute(router_gemm_kernel,
                         cudaFuncAttributeMaxDynamicSharedMemorySize, SMEM_BYTES);
    router_gemm_kernel<<<ROWS / TILE_R, NTHR, SMEM_BYTES>>>(X, W, probs, logits);

    thr_kernel<<<BATCH * NEXP, 512>>>();

    maskfill_kernel<<<ROWS / 8, 256>>>(probs, mask);
}

// round 13
// speedup vs baseline: 1.1594x; 1.0010x over previous
#include <cuda_runtime.h>
#include <cuda_fp16.h>
#include <cstdint>

// Problem constants
#define BATCH 4
#define SEQ   8192
#define DIM   4096
#define NEXP  64
#define CAP   256
#define ROWS  (BATCH * SEQ)      // 32768

// GEMM tiling (R12 config): 128 rows/CTA, 256 thr, KT=32, 2 CTA/SM
#define TILE_R 128
#define NTHR   256
#define KT     32
#define NCHUNK (DIM / KT)        // 128

// W pre-scaled by 2^10 in wconv; logits unscaled by 2^-10 (exact).
#define WSCALE   1024.0f
#define WUNSCALE 0.0009765625f

// smem: fp16 tiles, row stride 40 halves (80 bytes) -> conflict-free ldmatrix
#define AS_BYTE 80
#define AHI_OFF 0
#define ALO_OFF 10240
#define BHI_OFF 20480
#define BLO_OFF 25600
#define BUF_STRIDE 30720
#define SMEM_BYTES (2 * BUF_STRIDE)   // 61440

// epilogue smem reuse
#define PS_STRIDE 130
#define RED_OFF   34048           // Ps = 64*130*4 = 33280

// scratch
__device__ __half g_Whi[NEXP * DIM];                     // W hi (scaled fp16)
__device__ __half g_Wlo[NEXP * DIM];                     // W lo (scaled fp16)
__device__ float  g_probsT[(size_t)BATCH * NEXP * SEQ];  // [B][E][S]
__device__ float  g_thr[BATCH * NEXP];                   // per-(b,e) threshold

// ---------------------------------------------------------------------------
__device__ __forceinline__ uint32_t smem_u32(const void* p) {
    uint32_t a;
    asm("{ .reg .u64 t; cvta.to.shared.u64 t, %1; cvt.u32.u64 %0, t; }" : "=r"(a) : "l"(p));
    return a;
}
__device__ __forceinline__ void cp_async16(void* smem_dst, const void* gmem_src) {
    unsigned s = (unsigned)__cvta_generic_to_shared(smem_dst);
    asm volatile("cp.async.cg.shared.global [%0], [%1], 16;\n" :: "r"(s), "l"(gmem_src) : "memory");
}
__device__ __forceinline__ void cp_commit() {
    asm volatile("cp.async.commit_group;\n" ::: "memory");
}
__device__ __forceinline__ void cp_wait0() {
    asm volatile("cp.async.wait_group 0;\n" ::: "memory");
}

__device__ __forceinline__ void ldsm_x4(uint32_t& r0, uint32_t& r1, uint32_t& r2,
                                        uint32_t& r3, uint32_t addr) {
    asm volatile("ldmatrix.sync.aligned.m8n8.x4.shared.b16 {%0,%1,%2,%3}, [%4];"
                 : "=r"(r0), "=r"(r1), "=r"(r2), "=r"(r3) : "r"(addr));
}

__device__ __forceinline__ void mma_fp16(float* d, const uint32_t* a,
                                         uint32_t b0, uint32_t b1) {
    asm volatile("mma.sync.aligned.m16n8k16.row.col.f32.f16.f16.f32 "
                 "{%0,%1,%2,%3}, {%4,%5,%6,%7}, {%8,%9}, {%0,%1,%2,%3};"
                 : "+f"(d[0]), "+f"(d[1]), "+f"(d[2]), "+f"(d[3])
                 : "r"(a[0]), "r"(a[1]), "r"(a[2]), "r"(a[3]), "r"(b0), "r"(b1));
}

// ---------------------------------------------------------------------------
// Kernel 0: W fp32 -> scaled fp16 Dekker split (hi/lo), once per launch.
// ---------------------------------------------------------------------------
__global__ void __launch_bounds__(256)
wconv_kernel(const float* __restrict__ W)
{
    int i = blockIdx.x * 256 + threadIdx.x;     // one float2 per thread
    float2 w = *(const float2*)(W + 2 * i);
    w.x *= WSCALE; w.y *= WSCALE;
    __half2 h = __floats2half2_rn(w.x, w.y);
    float rx = w.x - __half2float(__low2half(h));
    float ry = w.y - __half2float(__high2half(h));
    __half2 l = __floats2half2_rn(rx, ry);
    *(__half2*)(g_Whi + 2 * i) = h;
    *(__half2*)(g_Wlo + 2 * i) = l;
}

// ---------------------------------------------------------------------------
// Kernel 1: HMMA fp16-split router GEMM + fused softmax (R12 base).
// Change vs R12: W tiles arrive via cp.async from pre-converted g_Whi/g_Wlo —
// no per-chunk W LDG-fp32 / convert / STS in the hot loop.
// 4x2 warp grid. Grid 256 x 256 threads, 2 CTAs/SM.
// ---------------------------------------------------------------------------
__global__ void __launch_bounds__(NTHR, 2)
router_gemm_kernel(const float* __restrict__ X,
                   float* __restrict__ probs_out, float* __restrict__ logits_out)
{
    extern __shared__ char smem[];
    const uint32_t sbase = smem_u32(smem);
    const int tid  = threadIdx.x;
    const int wid  = tid >> 5;
    const int lane = tid & 31;
    const int wr   = wid & 3;     // row group (32 rows)
    const int wc   = wid >> 2;    // expert group (32 experts)
    const int row0 = blockIdx.x * TILE_R;

    float d[2][4][4];
#pragma unroll
    for (int mf = 0; mf < 2; mf++)
#pragma unroll
        for (int g = 0; g < 4; g++)
#pragma unroll
            for (int j = 0; j < 4; j++) d[mf][g][j] = 0.f;

    uint32_t a_off[2], b_off[2];
#pragma unroll
    for (int mf = 0; mf < 2; mf++)
        a_off[mf] = (uint32_t)((wr * 32 + mf * 16 + ((lane >> 3) & 1) * 8 + (lane & 7)) * AS_BYTE
                               + ((lane >> 4) & 1) * 16);
#pragma unroll
    for (int bg = 0; bg < 2; bg++)
        b_off[bg] = (uint32_t)((wc * 32 + bg * 16 + ((lane >> 4) & 1) * 8 + (lane & 7)) * AS_BYTE
                               + ((lane >> 3) & 1) * 16);

    // X register staging (4 float4 per thread)
    float4 xr[4];

    auto load_chunk = [&](int t) {
        const int k0 = t * KT;
#pragma unroll
        for (int m = 0; m < 4; m++) {
            int f = tid + m * 256;           // float4 slot, 8 per row
            int r = f >> 3, c4 = f & 7;
            xr[m] = *(const float4*)(X + (size_t)(row0 + r) * DIM + k0 + c4 * 4);
        }
    };

    // W fill: 512 x 16B cp.async (hi 256 + lo 256); 2 per thread.
    auto fill_W = [&](int t, int buf) {
        char* bp = smem + buf * BUF_STRIDE;
        const int k0 = t * KT;
#pragma unroll
        for (int m = 0; m < 2; m++) {
            int i = tid + m * 256;          // 0..511
            int term = i >> 8;              // 0 = hi, 1 = lo
            int j    = i & 255;
            int e    = j >> 2;              // expert row 0..63
            int c16  = j & 3;               // 16B chunk within 64B row data
            char* dst = bp + (term ? BLO_OFF : BHI_OFF) + e * AS_BYTE + c16 * 16;
            const __half* src = (term ? g_Wlo : g_Whi) + (size_t)e * DIM + k0 + c16 * 8;
            cp_async16(dst, src);
        }
    };

    auto cvt_store = [&](float4 v, char* hi_b, char* lo_b, uint32_t byte_off) {
        __half2 h0 = __floats2half2_rn(v.x, v.y);
        __half2 h1 = __floats2half2_rn(v.z, v.w);
        float rx = v.x - __half2float(__low2half(h0));
        float ry = v.y - __half2float(__high2half(h0));
        float rz = v.z - __half2float(__low2half(h1));
        float rw = v.w - __half2float(__high2half(h1));
        __half2 l0 = __floats2half2_rn(rx, ry);
        __half2 l1 = __floats2half2_rn(rz, rw);
        *(uint2*)(hi_b + byte_off) = make_uint2(*(uint32_t*)&h0, *(uint32_t*)&h1);
        *(uint2*)(lo_b + byte_off) = make_uint2(*(uint32_t*)&l0, *(uint32_t*)&l1);
    };

    auto store_chunk = [&](int buf) {
        char* bp = smem + buf * BUF_STRIDE;
#pragma unroll
        for (int m = 0; m < 4; m++) {
            int f = tid + m * 256;
            int r = f >> 3, c4 = f & 7;
            cvt_store(xr[m], bp + AHI_OFF, bp + ALO_OFF, (uint32_t)(r * AS_BYTE + c4 * 8));
        }
    };

    auto compute_chunk = [&](int buf) {
        const uint32_t bb = sbase + buf * BUF_STRIDE;
#pragma unroll
        for (int ks = 0; ks < 2; ks++) {
            const uint32_t kb = ks * 32;
            uint32_t ah[2][4], al[2][4];
#pragma unroll
            for (int mf = 0; mf < 2; mf++) {
                ldsm_x4(ah[mf][0], ah[mf][1], ah[mf][2], ah[mf][3], bb + AHI_OFF + a_off[mf] + kb);
                ldsm_x4(al[mf][0], al[mf][1], al[mf][2], al[mf][3], bb + ALO_OFF + a_off[mf] + kb);
            }
#pragma unroll
            for (int bg = 0; bg < 2; bg++) {
                uint32_t bh[4], bl[4];
                ldsm_x4(bh[0], bh[1], bh[2], bh[3], bb + BHI_OFF + b_off[bg] + kb);
                ldsm_x4(bl[0], bl[1], bl[2], bl[3], bb + BLO_OFF + b_off[bg] + kb);
#pragma unroll
                for (int mf = 0; mf < 2; mf++) {
                    mma_fp16(d[mf][2 * bg],     ah[mf], bh[0], bh[1]);
                    mma_fp16(d[mf][2 * bg],     ah[mf], bl[0], bl[1]);
                    mma_fp16(d[mf][2 * bg],     al[mf], bh[0], bh[1]);
                    mma_fp16(d[mf][2 * bg + 1], ah[mf], bh[2], bh[3]);
                    mma_fp16(d[mf][2 * bg + 1], ah[mf], bl[2], bl[3]);
                    mma_fp16(d[mf][2 * bg + 1], al[mf], bh[2], bh[3]);
                }
            }
        }
    };

    // prologue: W(0) async + X(0) staged into buf0
    fill_W(0, 0); cp_commit();
    load_chunk(0);
    store_chunk(0);
    cp_wait0();
    __syncthreads();

    for (int t = 0; t < NCHUNK; t++) {
        const bool more = (t + 1 < NCHUNK);
        if (more) { fill_W(t + 1, (t + 1) & 1); cp_commit(); load_chunk(t + 1); }
        compute_chunk(t & 1);
        if (more) { store_chunk((t + 1) & 1); cp_wait0(); }
        __syncthreads();
    }

    // ------------------------------------------------------------------
    // Epilogue: softmax across the 2 expert-group warps via smem exchange.
    // ------------------------------------------------------------------
    float* Ps     = (float*)smem;                 // [64][130]
    float* sm_max = (float*)(smem + RED_OFF);     // [128][2]
    float* sm_sum = sm_max + 256;                 // [128][2]
    const int q  = lane >> 2;
    const int c2 = (lane & 3) * 2;
    float pmax[2][2];

#pragma unroll
    for (int mf = 0; mf < 2; mf++)
#pragma unroll
    for (int half = 0; half < 2; half++) {
        const int r = wr * 32 + mf * 16 + q + half * 8;
        float v[8];
#pragma unroll
        for (int g = 0; g < 4; g++) {
            v[2 * g]     = d[mf][g][2 * half]     * WUNSCALE;
            v[2 * g + 1] = d[mf][g][2 * half + 1] * WUNSCALE;
        }
        float mx = v[0];
#pragma unroll
        for (int c = 1; c < 8; c++) mx = fmaxf(mx, v[c]);
        mx = fmaxf(mx, __shfl_xor_sync(0xFFFFFFFFu, mx, 1));
        mx = fmaxf(mx, __shfl_xor_sync(0xFFFFFFFFu, mx, 2));
        float ssum = 0.f;
#pragma unroll
        for (int c = 0; c < 8; c++) {
            float e = expf(v[c] - mx);
            d[mf][c >> 1][2 * half + (c & 1)] = e;   // cache exp
            ssum += e;
        }
        ssum += __shfl_xor_sync(0xFFFFFFFFu, ssum, 1);
        ssum += __shfl_xor_sync(0xFFFFFFFFu, ssum, 2);
        pmax[mf][half] = mx;

        const size_t grow = (size_t)(row0 + r) * NEXP + wc * 32;
#pragma unroll
        for (int g = 0; g < 4; g++)
            *(float2*)(logits_out + grow + g * 8 + c2) = make_float2(v[2 * g], v[2 * g + 1]);

        if ((lane & 3) == 0) {
            sm_max[r * 2 + wc] = mx;
            sm_sum[r * 2 + wc] = ssum;
        }
    }
    __syncthreads();

#pragma unroll
    for (int mf = 0; mf < 2; mf++)
#pragma unroll
    for (int half = 0; half < 2; half++) {
        const int r = wr * 32 + mf * 16 + q + half * 8;
        float m0 = sm_max[r * 2], m1 = sm_max[r * 2 + 1];
        float s0 = sm_sum[r * 2], s1 = sm_sum[r * 2 + 1];
        float M = fmaxf(m0, m1);
        float S = s0 * expf(m0 - M) + s1 * expf(m1 - M);
        float scale = expf(pmax[mf][half] - M) / S;

        const size_t grow = (size_t)(row0 + r) * NEXP + wc * 32;
#pragma unroll
        for (int g = 0; g < 4; g++) {
            const int col = wc * 32 + g * 8 + c2;
            float p0 = d[mf][g][2 * half]     * scale;
            float p1 = d[mf][g][2 * half + 1] * scale;
            *(float2*)(probs_out + grow + g * 8 + c2) = make_float2(p0, p1);
            Ps[col * PS_STRIDE + r]       = p0;
            Ps[(col + 1) * PS_STRIDE + r] = p1;
        }
    }
    __syncthreads();

    // coalesced transpose write: g_probsT[b][e][s]
    const int bb2 = row0 >> 13;
    const int s0i = row0 & (SEQ - 1);
#pragma unroll
    for (int m = 0; m < 32; m++) {
        int idx = tid + m * NTHR;       // 0..8191
        int e = idx >> 7, r = idx & 127;
        g_probsT[((size_t)(bb2 * NEXP + e)) * SEQ + s0i + r] = Ps[e * PS_STRIDE + r];
    }
}

// ---------------------------------------------------------------------------
// Kernel 2: per-(b,e) exact top-CAP radix-select threshold -> g_thr.
// ---------------------------------------------------------------------------
__global__ void __launch_bounds__(512)
thr_kernel()
{
    __shared__ unsigned vals[SEQ];
    __shared__ unsigned hist[256];
    __shared__ unsigned sel_prefix, sel_remaining;

    const int be  = blockIdx.x;
    const int tid = threadIdx.x;
    const int lane = tid & 31;
    const unsigned* col = (const unsigned*)(g_probsT + (size_t)be * SEQ);

    for (int i = tid; i < SEQ; i += 512) vals[i] = col[i];
    if (tid == 0) { sel_prefix = 0u; sel_remaining = CAP; }
    __syncthreads();

    for (int pass = 0; pass < 4; pass++) {
        const int shift = 24 - 8 * pass;
        const unsigned himask = pass ? (0xFFFFFFFFu << (shift + 8)) : 0u;
        if (tid < 256) hist[tid] = 0u;
        __syncthreads();
        const unsigned pfx = sel_prefix;
        for (int i = tid; i < SEQ; i += 512) {
            unsigned u = vals[i];
            if ((u & himask) == pfx)
                atomicAdd(&hist[(u >> shift) & 255u], 1u);
        }
        __syncthreads();

        if (tid < 32) {
            unsigned b[8], s[8];
#pragma unroll
            for (int k = 0; k < 8; k++) b[k] = hist[lane * 8 + k];
            s[7] = b[7];
#pragma unroll
            for (int k = 6; k >= 0; k--) s[k] = b[k] + s[k + 1];
            unsigned T = s[0];
            unsigned incl = T;
#pragma unroll
            for (int off = 1; off < 32; off <<= 1) {
                unsigned v = __shfl_down_sync(0xFFFFFFFFu, incl, off);
                if (lane + off < 32) incl += v;
            }
            const unsigned excl = incl - T;
            const unsigned rem = sel_remaining;
#pragma unroll
            for (int k = 0; k < 8; k++) {
                unsigned suf = excl + s[k];
                unsigned nxt = suf - b[k];
                if (suf >= rem && nxt < rem) {
                    sel_prefix = pfx | ((unsigned)(lane * 8 + k) << shift);
                    sel_remaining = rem - nxt;
                }
            }
        }
        __syncthreads();
    }

    if (tid == 0) g_thr[be] = __uint_as_float(sel_prefix);
}

// ---------------------------------------------------------------------------
// Kernel 3: dense mask fill, loop-free: one warp per token.
// mask[b,s,0] = any_e(probs[b,s,e] >= thr[b,e]); other channels 0.
// ---------------------------------------------------------------------------
__global__ void __launch_bounds__(256)
maskfill_kernel(const float* __restrict__ probs, float* __restrict__ mask)
{
    __shared__ float thr[NEXP];
    const int tid  = threadIdx.x;
    const int lane = tid & 31;
    const int wid  = tid >> 5;
    const int tok  = blockIdx.x * 8 + wid;      // 8 tokens per block
    const int b    = (blockIdx.x * 8) >> 13;    // same batch across block

    if (tid < NEXP) thr[tid] = g_thr[b * NEXP + tid];
    __syncthreads();

    float2 p = *(const float2*)(probs + (size_t)tok * NEXP + 2 * lane);
    bool sel = (p.x >= thr[2 * lane]) || (p.y >= thr[2 * lane + 1]);
    unsigned any = __ballot_sync(0xFFFFFFFFu, sel);
    float2 o = make_float2(0.f, 0.f);
    if (lane == 0 && any) o.x = 1.0f;
    *(float2*)(mask + (size_t)tok * NEXP + 2 * lane) = o;
}

// ---------------------------------------------------------------------------
extern "C" void kernel_launch(void* const* d_in, const int* in_sizes, int n_in,
                              void* d_out, int out_size)
{
    const float* X = (const float*)d_in[0];   // [4, 8192, 4096]
    const float* W = (const float*)d_in[1];   // [64, 4096]

    float* mask   = (float*)d_out;
    float* probs  = mask  + (size_t)BATCH * SEQ * NEXP;
    float* logits = probs + (size_t)BATCH * SEQ * NEXP;

    // W -> scaled fp16 hi/lo (131072 float2 elems / 256 thr = 512 blocks)
    wconv_kernel<<<(NEXP * DIM / 2) / 256, 256>>>(W);

    cudaFuncSetAttribute(router_gemm_kernel,
                         cudaFuncAttributeMaxDynamicSharedMemorySize, SMEM_BYTES);
    router_gemm_kernel<<<ROWS / TILE_R, NTHR, SMEM_BYTES>>>(X, probs, logits);

    thr_kernel<<<BATCH * NEXP, 512>>>();

    maskfill_kernel<<<ROWS / 8, 256>>>(probs, mask);
}

// round 14
// speedup vs baseline: 1.2000x; 1.0350x over previous
#include <cuda_runtime.h>
#include <cuda_fp16.h>
#include <cstdint>

// Problem constants
#define BATCH 4
#define SEQ   8192
#define DIM   4096
#define NEXP  64
#define CAP   256
#define ROWS  (BATCH * SEQ)      // 32768

// GEMM tiling (R13 config): 128 rows/CTA, 256 thr, KT=32, 2 CTA/SM
#define TILE_R 128
#define NTHR   256
#define KT     32
#define NCHUNK (DIM / KT)        // 128

// W pre-scaled by 2^10 in wconv; logits unscaled by 2^-10 (exact).
#define WSCALE   1024.0f
#define WUNSCALE 0.0009765625f

// smem: fp16 tiles, row stride 40 halves (80 bytes) -> conflict-free ldmatrix
#define AS_BYTE 80
#define AHI_OFF 0
#define ALO_OFF 10240
#define BHI_OFF 20480
#define BLO_OFF 25600
#define BUF_STRIDE 30720
#define SMEM_BYTES (2 * BUF_STRIDE)   // 61440

// epilogue smem reuse
#define PS_STRIDE 130
#define RED_OFF   34048           // Ps = 64*130*4 = 33280

// scratch
__device__ __half g_Whi[NEXP * DIM];                     // W hi (scaled fp16)
__device__ __half g_Wlo[NEXP * DIM];                     // W lo (scaled fp16)
__device__ float  g_probsT[(size_t)BATCH * NEXP * SEQ];  // [B][E][S]
__device__ float  g_thr[BATCH * NEXP];                   // per-(b,e) threshold

// ---------------------------------------------------------------------------
__device__ __forceinline__ uint32_t smem_u32(const void* p) {
    uint32_t a;
    asm("{ .reg .u64 t; cvta.to.shared.u64 t, %1; cvt.u32.u64 %0, t; }" : "=r"(a) : "l"(p));
    return a;
}
__device__ __forceinline__ void cp_async16(void* smem_dst, const void* gmem_src) {
    unsigned s = (unsigned)__cvta_generic_to_shared(smem_dst);
    asm volatile("cp.async.cg.shared.global [%0], [%1], 16;\n" :: "r"(s), "l"(gmem_src) : "memory");
}
__device__ __forceinline__ void cp_commit() {
    asm volatile("cp.async.commit_group;\n" ::: "memory");
}
__device__ __forceinline__ void cp_wait0() {
    asm volatile("cp.async.wait_group 0;\n" ::: "memory");
}

__device__ __forceinline__ void ldsm_x4(uint32_t& r0, uint32_t& r1, uint32_t& r2,
                                        uint32_t& r3, uint32_t addr) {
    asm volatile("ldmatrix.sync.aligned.m8n8.x4.shared.b16 {%0,%1,%2,%3}, [%4];"
                 : "=r"(r0), "=r"(r1), "=r"(r2), "=r"(r3) : "r"(addr));
}

__device__ __forceinline__ void mma_fp16(float* d, const uint32_t* a,
                                         uint32_t b0, uint32_t b1) {
    asm volatile("mma.sync.aligned.m16n8k16.row.col.f32.f16.f16.f32 "
                 "{%0,%1,%2,%3}, {%4,%5,%6,%7}, {%8,%9}, {%0,%1,%2,%3};"
                 : "+f"(d[0]), "+f"(d[1]), "+f"(d[2]), "+f"(d[3])
                 : "r"(a[0]), "r"(a[1]), "r"(a[2]), "r"(a[3]), "r"(b0), "r"(b1));
}

// ---------------------------------------------------------------------------
// Kernel 0: W fp32 -> scaled fp16 Dekker split (hi/lo), once per launch.
// ---------------------------------------------------------------------------
__global__ void __launch_bounds__(256)
wconv_kernel(const float* __restrict__ W)
{
    int i = blockIdx.x * 256 + threadIdx.x;     // one float2 per thread
    float2 w = *(const float2*)(W + 2 * i);
    w.x *= WSCALE; w.y *= WSCALE;
    __half2 h = __floats2half2_rn(w.x, w.y);
    float rx = w.x - __half2float(__low2half(h));
    float ry = w.y - __half2float(__high2half(h));
    __half2 l = __floats2half2_rn(rx, ry);
    *(__half2*)(g_Whi + 2 * i) = h;
    *(__half2*)(g_Wlo + 2 * i) = l;
}

// ---------------------------------------------------------------------------
// Kernel 1: HMMA fp16-split router GEMM + fused softmax (identical to R13).
// W tiles via cp.async from pre-converted g_Whi/g_Wlo; X: LDG->split->STS.
// 4x2 warp grid. Grid 256 x 256 threads, 2 CTAs/SM.
// ---------------------------------------------------------------------------
__global__ void __launch_bounds__(NTHR, 2)
router_gemm_kernel(const float* __restrict__ X,
                   float* __restrict__ probs_out, float* __restrict__ logits_out)
{
    extern __shared__ char smem[];
    const uint32_t sbase = smem_u32(smem);
    const int tid  = threadIdx.x;
    const int wid  = tid >> 5;
    const int lane = tid & 31;
    const int wr   = wid & 3;     // row group (32 rows)
    const int wc   = wid >> 2;    // expert group (32 experts)
    const int row0 = blockIdx.x * TILE_R;

    float d[2][4][4];
#pragma unroll
    for (int mf = 0; mf < 2; mf++)
#pragma unroll
        for (int g = 0; g < 4; g++)
#pragma unroll
            for (int j = 0; j < 4; j++) d[mf][g][j] = 0.f;

    uint32_t a_off[2], b_off[2];
#pragma unroll
    for (int mf = 0; mf < 2; mf++)
        a_off[mf] = (uint32_t)((wr * 32 + mf * 16 + ((lane >> 3) & 1) * 8 + (lane & 7)) * AS_BYTE
                               + ((lane >> 4) & 1) * 16);
#pragma unroll
    for (int bg = 0; bg < 2; bg++)
        b_off[bg] = (uint32_t)((wc * 32 + bg * 16 + ((lane >> 4) & 1) * 8 + (lane & 7)) * AS_BYTE
                               + ((lane >> 3) & 1) * 16);

    float4 xr[4];   // X register staging

    auto load_chunk = [&](int t) {
        const int k0 = t * KT;
#pragma unroll
        for (int m = 0; m < 4; m++) {
            int f = tid + m * 256;           // float4 slot, 8 per row
            int r = f >> 3, c4 = f & 7;
            xr[m] = *(const float4*)(X + (size_t)(row0 + r) * DIM + k0 + c4 * 4);
        }
    };

    auto fill_W = [&](int t, int buf) {
        char* bp = smem + buf * BUF_STRIDE;
        const int k0 = t * KT;
#pragma unroll
        for (int m = 0; m < 2; m++) {
            int i = tid + m * 256;          // 0..511
            int term = i >> 8;              // 0 = hi, 1 = lo
            int j    = i & 255;
            int e    = j >> 2;              // expert row 0..63
            int c16  = j & 3;               // 16B chunk within 64B row data
            char* dst = bp + (term ? BLO_OFF : BHI_OFF) + e * AS_BYTE + c16 * 16;
            const __half* src = (term ? g_Wlo : g_Whi) + (size_t)e * DIM + k0 + c16 * 8;
            cp_async16(dst, src);
        }
    };

    auto cvt_store = [&](float4 v, char* hi_b, char* lo_b, uint32_t byte_off) {
        __half2 h0 = __floats2half2_rn(v.x, v.y);
        __half2 h1 = __floats2half2_rn(v.z, v.w);
        float rx = v.x - __half2float(__low2half(h0));
        float ry = v.y - __half2float(__high2half(h0));
        float rz = v.z - __half2float(__low2half(h1));
        float rw = v.w - __half2float(__high2half(h1));
        __half2 l0 = __floats2half2_rn(rx, ry);
        __half2 l1 = __floats2half2_rn(rz, rw);
        *(uint2*)(hi_b + byte_off) = make_uint2(*(uint32_t*)&h0, *(uint32_t*)&h1);
        *(uint2*)(lo_b + byte_off) = make_uint2(*(uint32_t*)&l0, *(uint32_t*)&l1);
    };

    auto store_chunk = [&](int buf) {
        char* bp = smem + buf * BUF_STRIDE;
#pragma unroll
        for (int m = 0; m < 4; m++) {
            int f = tid + m * 256;
            int r = f >> 3, c4 = f & 7;
            cvt_store(xr[m], bp + AHI_OFF, bp + ALO_OFF, (uint32_t)(r * AS_BYTE + c4 * 8));
        }
    };

    auto compute_chunk = [&](int buf) {
        const uint32_t bb = sbase + buf * BUF_STRIDE;
#pragma unroll
        for (int ks = 0; ks < 2; ks++) {
            const uint32_t kb = ks * 32;
            uint32_t ah[2][4], al[2][4];
#pragma unroll
            for (int mf = 0; mf < 2; mf++) {
                ldsm_x4(ah[mf][0], ah[mf][1], ah[mf][2], ah[mf][3], bb + AHI_OFF + a_off[mf] + kb);
                ldsm_x4(al[mf][0], al[mf][1], al[mf][2], al[mf][3], bb + ALO_OFF + a_off[mf] + kb);
            }
#pragma unroll
            for (int bg = 0; bg < 2; bg++) {
                uint32_t bh[4], bl[4];
                ldsm_x4(bh[0], bh[1], bh[2], bh[3], bb + BHI_OFF + b_off[bg] + kb);
                ldsm_x4(bl[0], bl[1], bl[2], bl[3], bb + BLO_OFF + b_off[bg] + kb);
#pragma unroll
                for (int mf = 0; mf < 2; mf++) {
                    mma_fp16(d[mf][2 * bg],     ah[mf], bh[0], bh[1]);
                    mma_fp16(d[mf][2 * bg],     ah[mf], bl[0], bl[1]);
                    mma_fp16(d[mf][2 * bg],     al[mf], bh[0], bh[1]);
                    mma_fp16(d[mf][2 * bg + 1], ah[mf], bh[2], bh[3]);
                    mma_fp16(d[mf][2 * bg + 1], ah[mf], bl[2], bl[3]);
                    mma_fp16(d[mf][2 * bg + 1], al[mf], bh[2], bh[3]);
                }
            }
        }
    };

    fill_W(0, 0); cp_commit();
    load_chunk(0);
    store_chunk(0);
    cp_wait0();
    __syncthreads();

    for (int t = 0; t < NCHUNK; t++) {
        const bool more = (t + 1 < NCHUNK);
        if (more) { fill_W(t + 1, (t + 1) & 1); cp_commit(); load_chunk(t + 1); }
        compute_chunk(t & 1);
        if (more) { store_chunk((t + 1) & 1); cp_wait0(); }
        __syncthreads();
    }

    // Epilogue: softmax across the 2 expert-group warps via smem exchange.
    float* Ps     = (float*)smem;                 // [64][130]
    float* sm_max = (float*)(smem + RED_OFF);     // [128][2]
    float* sm_sum = sm_max + 256;                 // [128][2]
    const int q  = lane >> 2;
    const int c2 = (lane & 3) * 2;
    float pmax[2][2];

#pragma unroll
    for (int mf = 0; mf < 2; mf++)
#pragma unroll
    for (int half = 0; half < 2; half++) {
        const int r = wr * 32 + mf * 16 + q + half * 8;
        float v[8];
#pragma unroll
        for (int g = 0; g < 4; g++) {
            v[2 * g]     = d[mf][g][2 * half]     * WUNSCALE;
            v[2 * g + 1] = d[mf][g][2 * half + 1] * WUNSCALE;
        }
        float mx = v[0];
#pragma unroll
        for (int c = 1; c < 8; c++) mx = fmaxf(mx, v[c]);
        mx = fmaxf(mx, __shfl_xor_sync(0xFFFFFFFFu, mx, 1));
        mx = fmaxf(mx, __shfl_xor_sync(0xFFFFFFFFu, mx, 2));
        float ssum = 0.f;
#pragma unroll
        for (int c = 0; c < 8; c++) {
            float e = expf(v[c] - mx);
            d[mf][c >> 1][2 * half + (c & 1)] = e;   // cache exp
            ssum += e;
        }
        ssum += __shfl_xor_sync(0xFFFFFFFFu, ssum, 1);
        ssum += __shfl_xor_sync(0xFFFFFFFFu, ssum, 2);
        pmax[mf][half] = mx;

        const size_t grow = (size_t)(row0 + r) * NEXP + wc * 32;
#pragma unroll
        for (int g = 0; g < 4; g++)
            *(float2*)(logits_out + grow + g * 8 + c2) = make_float2(v[2 * g], v[2 * g + 1]);

        if ((lane & 3) == 0) {
            sm_max[r * 2 + wc] = mx;
            sm_sum[r * 2 + wc] = ssum;
        }
    }
    __syncthreads();

#pragma unroll
    for (int mf = 0; mf < 2; mf++)
#pragma unroll
    for (int half = 0; half < 2; half++) {
        const int r = wr * 32 + mf * 16 + q + half * 8;
        float m0 = sm_max[r * 2], m1 = sm_max[r * 2 + 1];
        float s0 = sm_sum[r * 2], s1 = sm_sum[r * 2 + 1];
        float M = fmaxf(m0, m1);
        float S = s0 * expf(m0 - M) + s1 * expf(m1 - M);
        float scale = expf(pmax[mf][half] - M) / S;

        const size_t grow = (size_t)(row0 + r) * NEXP + wc * 32;
#pragma unroll
        for (int g = 0; g < 4; g++) {
            const int col = wc * 32 + g * 8 + c2;
            float p0 = d[mf][g][2 * half]     * scale;
            float p1 = d[mf][g][2 * half + 1] * scale;
            *(float2*)(probs_out + grow + g * 8 + c2) = make_float2(p0, p1);
            Ps[col * PS_STRIDE + r]       = p0;
            Ps[(col + 1) * PS_STRIDE + r] = p1;
        }
    }
    __syncthreads();

    const int bb2 = row0 >> 13;
    const int s0i = row0 & (SEQ - 1);
#pragma unroll
    for (int m = 0; m < 32; m++) {
        int idx = tid + m * NTHR;       // 0..8191
        int e = idx >> 7, r = idx & 127;
        g_probsT[((size_t)(bb2 * NEXP + e)) * SEQ + s0i + r] = Ps[e * PS_STRIDE + r];
    }
}

// ---------------------------------------------------------------------------
// Kernel 2: per-(b,e) exact top-CAP radix-select threshold -> g_thr.
// Values held in 16 registers/thread (no smem round trips across passes).
// ---------------------------------------------------------------------------
__global__ void __launch_bounds__(512)
thr_kernel()
{
    __shared__ unsigned hist[256];
    __shared__ unsigned sel_prefix, sel_remaining;

    const int be   = blockIdx.x;
    const int tid  = threadIdx.x;
    const int lane = tid & 31;
    const unsigned* col = (const unsigned*)(g_probsT + (size_t)be * SEQ);

    unsigned v[16];
#pragma unroll
    for (int m = 0; m < 16; m++) v[m] = col[tid + m * 512];
    if (tid == 0) { sel_prefix = 0u; sel_remaining = CAP; }
    __syncthreads();

    for (int pass = 0; pass < 4; pass++) {
        const int shift = 24 - 8 * pass;
        const unsigned himask = pass ? (0xFFFFFFFFu << (shift + 8)) : 0u;
        if (tid < 256) hist[tid] = 0u;
        __syncthreads();
        const unsigned pfx = sel_prefix;
#pragma unroll
        for (int m = 0; m < 16; m++) {
            if ((v[m] & himask) == pfx)
                atomicAdd(&hist[(v[m] >> shift) & 255u], 1u);
        }
        __syncthreads();

        if (tid < 32) {
            unsigned b[8], s[8];
#pragma unroll
            for (int k = 0; k < 8; k++) b[k] = hist[lane * 8 + k];
            s[7] = b[7];
#pragma unroll
            for (int k = 6; k >= 0; k--) s[k] = b[k] + s[k + 1];
            unsigned T = s[0];
            unsigned incl = T;
#pragma unroll
            for (int off = 1; off < 32; off <<= 1) {
                unsigned u = __shfl_down_sync(0xFFFFFFFFu, incl, off);
                if (lane + off < 32) incl += u;
            }
            const unsigned excl = incl - T;
            const unsigned rem = sel_remaining;
#pragma unroll
            for (int k = 0; k < 8; k++) {
                unsigned suf = excl + s[k];
                unsigned nxt = suf - b[k];
                if (suf >= rem && nxt < rem) {
                    sel_prefix = pfx | ((unsigned)(lane * 8 + k) << shift);
                    sel_remaining = rem - nxt;
                }
            }
        }
        __syncthreads();
    }

    if (tid == 0) g_thr[be] = __uint_as_float(sel_prefix);
}

// ---------------------------------------------------------------------------
// Kernel 3: dense mask fill. 4 independent tokens per warp (MLP=4 hides L2
// latency). mask[b,s,0] = any_e(probs[b,s,e] >= thr[b,e]); other channels 0.
// ---------------------------------------------------------------------------
__global__ void __launch_bounds__(256)
maskfill_kernel(const float* __restrict__ probs, float* __restrict__ mask)
{
    __shared__ float thr[NEXP];
    const int tid  = threadIdx.x;
    const int lane = tid & 31;
    const int wid  = tid >> 5;
    const int tok0 = blockIdx.x * 32 + wid * 4;   // 32 tokens per block
    const int b    = (blockIdx.x * 32) >> 13;     // same batch across block

    if (tid < NEXP) thr[tid] = g_thr[b * NEXP + tid];
    __syncthreads();

    const float t0 = thr[2 * lane], t1 = thr[2 * lane + 1];
    float2 p[4];
#pragma unroll
    for (int i = 0; i < 4; i++)
        p[i] = *(const float2*)(probs + (size_t)(tok0 + i) * NEXP + 2 * lane);
#pragma unroll
    for (int i = 0; i < 4; i++) {
        bool sel = (p[i].x >= t0) || (p[i].y >= t1);
        unsigned any = __ballot_sync(0xFFFFFFFFu, sel);
        float2 o = make_float2(0.f, 0.f);
        if (lane == 0 && any) o.x = 1.0f;
        *(float2*)(mask + (size_t)(tok0 + i) * NEXP + 2 * lane) = o;
    }
}

// ---------------------------------------------------------------------------
extern "C" void kernel_launch(void* const* d_in, const int* in_sizes, int n_in,
                              void* d_out, int out_size)
{
    const float* X = (const float*)d_in[0];   // [4, 8192, 4096]
    const float* W = (const float*)d_in[1];   // [64, 4096]

    float* mask   = (float*)d_out;
    float* probs  = mask  + (size_t)BATCH * SEQ * NEXP;
    float* logits = probs + (size_t)BATCH * SEQ * NEXP;

    // W -> scaled fp16 hi/lo
    wconv_kernel<<<(NEXP * DIM / 2) / 256, 256>>>(W);

    cudaFuncSetAttribute(router_gemm_kernel,
                         cudaFuncAttributeMaxDynamicSharedMemorySize, SMEM_BYTES);
    router_gemm_kernel<<<ROWS / TILE_R, NTHR, SMEM_BYTES>>>(X, probs, logits);

    thr_kernel<<<BATCH * NEXP, 512>>>();

    maskfill_kernel<<<ROWS / 32, 256>>>(probs, mask);
}

// round 15
// speedup vs baseline: 1.2111x; 1.0093x over previous
#include <cuda_runtime.h>
#include <cuda_fp16.h>
#include <cstdint>

// Problem constants
#define BATCH 4
#define SEQ   8192
#define DIM   4096
#define NEXP  64
#define CAP   256
#define ROWS  (BATCH * SEQ)      // 32768

// GEMM tiling (R14 config): 128 rows/CTA, 256 thr, KT=32, 2 CTA/SM
#define TILE_R 128
#define NTHR   256
#define KT     32
#define NCHUNK (DIM / KT)        // 128

// W pre-scaled by 2^10 in prep; logits unscaled by 2^-10 (exact).
#define WSCALE   1024.0f
#define WUNSCALE 0.0009765625f

// smem: fp16 tiles, row stride 40 halves (80 bytes) -> conflict-free ldmatrix
#define AS_BYTE 80
#define AHI_OFF 0
#define ALO_OFF 10240
#define BHI_OFF 20480
#define BLO_OFF 25600
#define BUF_STRIDE 30720
#define SMEM_BYTES (2 * BUF_STRIDE)   // 61440

// epilogue smem reuse
#define PS_STRIDE 130
#define RED_OFF   34048           // Ps = 64*130*4 = 33280

// prep kernel block split
#define WCONV_BLKS 512            // 512*256 float2 = 64*4096 W elements
#define ZERO_BLKS  2048           // 2048*256*16B = 8 MB mask
#define PREP_BLKS  (WCONV_BLKS + ZERO_BLKS)

// scratch
__device__ __half g_Whi[NEXP * DIM];                     // W hi (scaled fp16)
__device__ __half g_Wlo[NEXP * DIM];                     // W lo (scaled fp16)
__device__ float  g_probsT[(size_t)BATCH * NEXP * SEQ];  // [B][E][S]

// ---------------------------------------------------------------------------
__device__ __forceinline__ uint32_t smem_u32(const void* p) {
    uint32_t a;
    asm("{ .reg .u64 t; cvta.to.shared.u64 t, %1; cvt.u32.u64 %0, t; }" : "=r"(a) : "l"(p));
    return a;
}
__device__ __forceinline__ void cp_async16(void* smem_dst, const void* gmem_src) {
    unsigned s = (unsigned)__cvta_generic_to_shared(smem_dst);
    asm volatile("cp.async.cg.shared.global [%0], [%1], 16;\n" :: "r"(s), "l"(gmem_src) : "memory");
}
__device__ __forceinline__ void cp_commit() {
    asm volatile("cp.async.commit_group;\n" ::: "memory");
}
__device__ __forceinline__ void cp_wait0() {
    asm volatile("cp.async.wait_group 0;\n" ::: "memory");
}

__device__ __forceinline__ void ldsm_x4(uint32_t& r0, uint32_t& r1, uint32_t& r2,
                                        uint32_t& r3, uint32_t addr) {
    asm volatile("ldmatrix.sync.aligned.m8n8.x4.shared.b16 {%0,%1,%2,%3}, [%4];"
                 : "=r"(r0), "=r"(r1), "=r"(r2), "=r"(r3) : "r"(addr));
}

__device__ __forceinline__ void mma_fp16(float* d, const uint32_t* a,
                                         uint32_t b0, uint32_t b1) {
    asm volatile("mma.sync.aligned.m16n8k16.row.col.f32.f16.f16.f32 "
                 "{%0,%1,%2,%3}, {%4,%5,%6,%7}, {%8,%9}, {%0,%1,%2,%3};"
                 : "+f"(d[0]), "+f"(d[1]), "+f"(d[2]), "+f"(d[3])
                 : "r"(a[0]), "r"(a[1]), "r"(a[2]), "r"(a[3]), "r"(b0), "r"(b1));
}

// ---------------------------------------------------------------------------
// Kernel 0: prep. Blocks [0, WCONV_BLKS): W fp32 -> scaled fp16 hi/lo split.
// Blocks [WCONV_BLKS, PREP_BLKS): zero the 8 MB mask region.
// ---------------------------------------------------------------------------
__global__ void __launch_bounds__(256)
prep_kernel(const float* __restrict__ W, float4* __restrict__ mask4)
{
    if (blockIdx.x < WCONV_BLKS) {
        int i = blockIdx.x * 256 + threadIdx.x;     // one float2 per thread
        float2 w = *(const float2*)(W + 2 * i);
        w.x *= WSCALE; w.y *= WSCALE;
        __half2 h = __floats2half2_rn(w.x, w.y);
        float rx = w.x - __half2float(__low2half(h));
        float ry = w.y - __half2float(__high2half(h));
        __half2 l = __floats2half2_rn(rx, ry);
        *(__half2*)(g_Whi + 2 * i) = h;
        *(__half2*)(g_Wlo + 2 * i) = l;
    } else {
        size_t i = (size_t)(blockIdx.x - WCONV_BLKS) * 256 + threadIdx.x;
        mask4[i] = make_float4(0.f, 0.f, 0.f, 0.f);
    }
}

// ---------------------------------------------------------------------------
// Kernel 1: HMMA fp16-split router GEMM + fused softmax (identical to R14).
// W tiles via cp.async from pre-converted g_Whi/g_Wlo; X: LDG->split->STS.
// 4x2 warp grid. Grid 256 x 256 threads, 2 CTAs/SM.
// ---------------------------------------------------------------------------
__global__ void __launch_bounds__(NTHR, 2)
router_gemm_kernel(const float* __restrict__ X,
                   float* __restrict__ probs_out, float* __restrict__ logits_out)
{
    extern __shared__ char smem[];
    const uint32_t sbase = smem_u32(smem);
    const int tid  = threadIdx.x;
    const int wid  = tid >> 5;
    const int lane = tid & 31;
    const int wr   = wid & 3;     // row group (32 rows)
    const int wc   = wid >> 2;    // expert group (32 experts)
    const int row0 = blockIdx.x * TILE_R;

    float d[2][4][4];
#pragma unroll
    for (int mf = 0; mf < 2; mf++)
#pragma unroll
        for (int g = 0; g < 4; g++)
#pragma unroll
            for (int j = 0; j < 4; j++) d[mf][g][j] = 0.f;

    uint32_t a_off[2], b_off[2];
#pragma unroll
    for (int mf = 0; mf < 2; mf++)
        a_off[mf] = (uint32_t)((wr * 32 + mf * 16 + ((lane >> 3) & 1) * 8 + (lane & 7)) * AS_BYTE
                               + ((lane >> 4) & 1) * 16);
#pragma unroll
    for (int bg = 0; bg < 2; bg++)
        b_off[bg] = (uint32_t)((wc * 32 + bg * 16 + ((lane >> 4) & 1) * 8 + (lane & 7)) * AS_BYTE
                               + ((lane >> 3) & 1) * 16);

    float4 xr[4];   // X register staging

    auto load_chunk = [&](int t) {
        const int k0 = t * KT;
#pragma unroll
        for (int m = 0; m < 4; m++) {
            int f = tid + m * 256;           // float4 slot, 8 per row
            int r = f >> 3, c4 = f & 7;
            xr[m] = *(const float4*)(X + (size_t)(row0 + r) * DIM + k0 + c4 * 4);
        }
    };

    auto fill_W = [&](int t, int buf) {
        char* bp = smem + buf * BUF_STRIDE;
        const int k0 = t * KT;
#pragma unroll
        for (int m = 0; m < 2; m++) {
            int i = tid + m * 256;          // 0..511
            int term = i >> 8;              // 0 = hi, 1 = lo
            int j    = i & 255;
            int e    = j >> 2;              // expert row 0..63
            int c16  = j & 3;               // 16B chunk within 64B row data
            char* dst = bp + (term ? BLO_OFF : BHI_OFF) + e * AS_BYTE + c16 * 16;
            const __half* src = (term ? g_Wlo : g_Whi) + (size_t)e * DIM + k0 + c16 * 8;
            cp_async16(dst, src);
        }
    };

    auto cvt_store = [&](float4 v, char* hi_b, char* lo_b, uint32_t byte_off) {
        __half2 h0 = __floats2half2_rn(v.x, v.y);
        __half2 h1 = __floats2half2_rn(v.z, v.w);
        float rx = v.x - __half2float(__low2half(h0));
        float ry = v.y - __half2float(__high2half(h0));
        float rz = v.z - __half2float(__low2half(h1));
        float rw = v.w - __half2float(__high2half(h1));
        __half2 l0 = __floats2half2_rn(rx, ry);
        __half2 l1 = __floats2half2_rn(rz, rw);
        *(uint2*)(hi_b + byte_off) = make_uint2(*(uint32_t*)&h0, *(uint32_t*)&h1);
        *(uint2*)(lo_b + byte_off) = make_uint2(*(uint32_t*)&l0, *(uint32_t*)&l1);
    };

    auto store_chunk = [&](int buf) {
        char* bp = smem + buf * BUF_STRIDE;
#pragma unroll
        for (int m = 0; m < 4; m++) {
            int f = tid + m * 256;
            int r = f >> 3, c4 = f & 7;
            cvt_store(xr[m], bp + AHI_OFF, bp + ALO_OFF, (uint32_t)(r * AS_BYTE + c4 * 8));
        }
    };

    auto compute_chunk = [&](int buf) {
        const uint32_t bb = sbase + buf * BUF_STRIDE;
#pragma unroll
        for (int ks = 0; ks < 2; ks++) {
            const uint32_t kb = ks * 32;
            uint32_t ah[2][4], al[2][4];
#pragma unroll
            for (int mf = 0; mf < 2; mf++) {
                ldsm_x4(ah[mf][0], ah[mf][1], ah[mf][2], ah[mf][3], bb + AHI_OFF + a_off[mf] + kb);
                ldsm_x4(al[mf][0], al[mf][1], al[mf][2], al[mf][3], bb + ALO_OFF + a_off[mf] + kb);
            }
#pragma unroll
            for (int bg = 0; bg < 2; bg++) {
                uint32_t bh[4], bl[4];
                ldsm_x4(bh[0], bh[1], bh[2], bh[3], bb + BHI_OFF + b_off[bg] + kb);
                ldsm_x4(bl[0], bl[1], bl[2], bl[3], bb + BLO_OFF + b_off[bg] + kb);
#pragma unroll
                for (int mf = 0; mf < 2; mf++) {
                    mma_fp16(d[mf][2 * bg],     ah[mf], bh[0], bh[1]);
                    mma_fp16(d[mf][2 * bg],     ah[mf], bl[0], bl[1]);
                    mma_fp16(d[mf][2 * bg],     al[mf], bh[0], bh[1]);
                    mma_fp16(d[mf][2 * bg + 1], ah[mf], bh[2], bh[3]);
                    mma_fp16(d[mf][2 * bg + 1], ah[mf], bl[2], bl[3]);
                    mma_fp16(d[mf][2 * bg + 1], al[mf], bh[2], bh[3]);
                }
            }
        }
    };

    fill_W(0, 0); cp_commit();
    load_chunk(0);
    store_chunk(0);
    cp_wait0();
    __syncthreads();

    for (int t = 0; t < NCHUNK; t++) {
        const bool more = (t + 1 < NCHUNK);
        if (more) { fill_W(t + 1, (t + 1) & 1); cp_commit(); load_chunk(t + 1); }
        compute_chunk(t & 1);
        if (more) { store_chunk((t + 1) & 1); cp_wait0(); }
        __syncthreads();
    }

    // Epilogue: softmax across the 2 expert-group warps via smem exchange.
    float* Ps     = (float*)smem;                 // [64][130]
    float* sm_max = (float*)(smem + RED_OFF);     // [128][2]
    float* sm_sum = sm_max + 256;                 // [128][2]
    const int q  = lane >> 2;
    const int c2 = (lane & 3) * 2;
    float pmax[2][2];

#pragma unroll
    for (int mf = 0; mf < 2; mf++)
#pragma unroll
    for (int half = 0; half < 2; half++) {
        const int r = wr * 32 + mf * 16 + q + half * 8;
        float v[8];
#pragma unroll
        for (int g = 0; g < 4; g++) {
            v[2 * g]     = d[mf][g][2 * half]     * WUNSCALE;
            v[2 * g + 1] = d[mf][g][2 * half + 1] * WUNSCALE;
        }
        float mx = v[0];
#pragma unroll
        for (int c = 1; c < 8; c++) mx = fmaxf(mx, v[c]);
        mx = fmaxf(mx, __shfl_xor_sync(0xFFFFFFFFu, mx, 1));
        mx = fmaxf(mx, __shfl_xor_sync(0xFFFFFFFFu, mx, 2));
        float ssum = 0.f;
#pragma unroll
        for (int c = 0; c < 8; c++) {
            float e = expf(v[c] - mx);
            d[mf][c >> 1][2 * half + (c & 1)] = e;   // cache exp
            ssum += e;
        }
        ssum += __shfl_xor_sync(0xFFFFFFFFu, ssum, 1);
        ssum += __shfl_xor_sync(0xFFFFFFFFu, ssum, 2);
        pmax[mf][half] = mx;

        const size_t grow = (size_t)(row0 + r) * NEXP + wc * 32;
#pragma unroll
        for (int g = 0; g < 4; g++)
            *(float2*)(logits_out + grow + g * 8 + c2) = make_float2(v[2 * g], v[2 * g + 1]);

        if ((lane & 3) == 0) {
            sm_max[r * 2 + wc] = mx;
            sm_sum[r * 2 + wc] = ssum;
        }
    }
    __syncthreads();

#pragma unroll
    for (int mf = 0; mf < 2; mf++)
#pragma unroll
    for (int half = 0; half < 2; half++) {
        const int r = wr * 32 + mf * 16 + q + half * 8;
        float m0 = sm_max[r * 2], m1 = sm_max[r * 2 + 1];
        float s0 = sm_sum[r * 2], s1 = sm_sum[r * 2 + 1];
        float M = fmaxf(m0, m1);
        float S = s0 * expf(m0 - M) + s1 * expf(m1 - M);
        float scale = expf(pmax[mf][half] - M) / S;

        const size_t grow = (size_t)(row0 + r) * NEXP + wc * 32;
#pragma unroll
        for (int g = 0; g < 4; g++) {
            const int col = wc * 32 + g * 8 + c2;
            float p0 = d[mf][g][2 * half]     * scale;
            float p1 = d[mf][g][2 * half + 1] * scale;
            *(float2*)(probs_out + grow + g * 8 + c2) = make_float2(p0, p1);
            Ps[col * PS_STRIDE + r]       = p0;
            Ps[(col + 1) * PS_STRIDE + r] = p1;
        }
    }
    __syncthreads();

    const int bb2 = row0 >> 13;
    const int s0i = row0 & (SEQ - 1);
#pragma unroll
    for (int m = 0; m < 32; m++) {
        int idx = tid + m * NTHR;       // 0..8191
        int e = idx >> 7, r = idx & 127;
        g_probsT[((size_t)(bb2 * NEXP + e)) * SEQ + s0i + r] = Ps[e * PS_STRIDE + r];
    }
}

// ---------------------------------------------------------------------------
// Kernel 2: per-(b,e) exact top-CAP radix select + mask scatter.
// Values in 16 registers/thread; after the threshold is found, selected
// tokens scatter mask[b,s,0] = 1 directly (mask pre-zeroed by prep_kernel;
// duplicate writers across experts store the identical value).
// ---------------------------------------------------------------------------
__global__ void __launch_bounds__(512)
thr_kernel(float* __restrict__ mask)
{
    __shared__ unsigned hist[256];
    __shared__ unsigned sel_prefix, sel_remaining;

    const int be   = blockIdx.x;
    const int tid  = threadIdx.x;
    const int lane = tid & 31;
    const unsigned* col = (const unsigned*)(g_probsT + (size_t)be * SEQ);

    unsigned v[16];
#pragma unroll
    for (int m = 0; m < 16; m++) v[m] = col[tid + m * 512];
    if (tid == 0) { sel_prefix = 0u; sel_remaining = CAP; }
    __syncthreads();

    for (int pass = 0; pass < 4; pass++) {
        const int shift = 24 - 8 * pass;
        const unsigned himask = pass ? (0xFFFFFFFFu << (shift + 8)) : 0u;
        if (tid < 256) hist[tid] = 0u;
        __syncthreads();
        const unsigned pfx = sel_prefix;
#pragma unroll
        for (int m = 0; m < 16; m++) {
            if ((v[m] & himask) == pfx)
                atomicAdd(&hist[(v[m] >> shift) & 255u], 1u);
        }
        __syncthreads();

        if (tid < 32) {
            unsigned b[8], s[8];
#pragma unroll
            for (int k = 0; k < 8; k++) b[k] = hist[lane * 8 + k];
            s[7] = b[7];
#pragma unroll
            for (int k = 6; k >= 0; k--) s[k] = b[k] + s[k + 1];
            unsigned T = s[0];
            unsigned incl = T;
#pragma unroll
            for (int off = 1; off < 32; off <<= 1) {
                unsigned u = __shfl_down_sync(0xFFFFFFFFu, incl, off);
                if (lane + off < 32) incl += u;
            }
            const unsigned excl = incl - T;
            const unsigned rem = sel_remaining;
#pragma unroll
            for (int k = 0; k < 8; k++) {
                unsigned suf = excl + s[k];
                unsigned nxt = suf - b[k];
                if (suf >= rem && nxt < rem) {
                    sel_prefix = pfx | ((unsigned)(lane * 8 + k) << shift);
                    sel_remaining = rem - nxt;
                }
            }
        }
        __syncthreads();
    }

    // scatter: selected tokens -> mask channel 0 (probs > 0 so uint order == float order)
    const unsigned thr = sel_prefix;
    const int bb = be >> 6;
    float* mrow = mask + (size_t)bb * SEQ * NEXP;
#pragma unroll
    for (int m = 0; m < 16; m++) {
        if (v[m] >= thr) {
            int s = tid + m * 512;
            mrow[(size_t)s * NEXP] = 1.0f;
        }
    }
}

// ---------------------------------------------------------------------------
extern "C" void kernel_launch(void* const* d_in, const int* in_sizes, int n_in,
                              void* d_out, int out_size)
{
    const float* X = (const float*)d_in[0];   // [4, 8192, 4096]
    const float* W = (const float*)d_in[1];   // [64, 4096]

    float* mask   = (float*)d_out;
    float* probs  = mask  + (size_t)BATCH * SEQ * NEXP;
    float* logits = probs + (size_t)BATCH * SEQ * NEXP;

    // prep: W -> scaled fp16 hi/lo  +  zero mask region
    prep_kernel<<<PREP_BLKS, 256>>>(W, (float4*)mask);

    cudaFuncSetAttribute(router_gemm_kernel,
                         cudaFuncAttributeMaxDynamicSharedMemorySize, SMEM_BYTES);
    router_gemm_kernel<<<ROWS / TILE_R, NTHR, SMEM_BYTES>>>(X, probs, logits);

    thr_kernel<<<BATCH * NEXP, 512>>>(mask);
}